// round 13
// baseline (speedup 1.0000x reference)
#include <cuda_runtime.h>
#include <cuda_bf16.h>
#include <cstdint>
#include <math.h>

#define S_LEN   2048
#define D_MODEL 2048
#define NH      16
#define DH      128
#define BATCH   2
#define TOKENS  (BATCH * S_LEN)   // 4096

// ---------------- scratch (device globals: allocation-free) ----------------
__device__ float g_Q[TOKENS * D_MODEL];
__device__ float g_K[TOKENS * D_MODEL];
__device__ float g_V[TOKENS * D_MODEL];
__device__ float g_O[TOKENS * D_MODEL];
__device__ __nv_bfloat16 g_Ah[TOKENS * D_MODEL];
__device__ __nv_bfloat16 g_Al[TOKENS * D_MODEL];
__device__ __nv_bfloat16 g_Bh[D_MODEL * D_MODEL];
__device__ __nv_bfloat16 g_Bl[D_MODEL * D_MODEL];
__device__ __nv_bfloat16 g_Qh[TOKENS * D_MODEL];
__device__ __nv_bfloat16 g_Ql[TOKENS * D_MODEL];
__device__ __nv_bfloat16 g_Kh[TOKENS * D_MODEL];
__device__ __nv_bfloat16 g_Kl[TOKENS * D_MODEL];
__device__ __nv_bfloat16 g_Vh[TOKENS * D_MODEL];
__device__ __nv_bfloat16 g_Vl[TOKENS * D_MODEL];
__device__ float2 g_cs[S_LEN * 64];

// ---------------- common asm helpers ---------------------------------------
#define MMA16816(d, a, b)                                                     \
    asm volatile(                                                             \
        "mma.sync.aligned.m16n8k16.row.col.f32.bf16.bf16.f32 "                \
        "{%0,%1,%2,%3},{%4,%5,%6,%7},{%8,%9},{%0,%1,%2,%3};\n"                \
        : "+f"(d[0]), "+f"(d[1]), "+f"(d[2]), "+f"(d[3])                      \
        : "r"(a[0]), "r"(a[1]), "r"(a[2]), "r"(a[3]), "r"(b[0]), "r"(b[1]))

#define LDSM_X4(d0, d1, d2, d3, addr)                                         \
    asm volatile("ldmatrix.sync.aligned.m8n8.x4.shared.b16 {%0,%1,%2,%3}, [%4];" \
                 : "=r"(d0), "=r"(d1), "=r"(d2), "=r"(d3) : "r"(addr))

#define LDSM_X4_T(d0, d1, d2, d3, addr)                                       \
    asm volatile("ldmatrix.sync.aligned.m8n8.x4.trans.shared.b16 {%0,%1,%2,%3}, [%4];" \
                 : "=r"(d0), "=r"(d1), "=r"(d2), "=r"(d3) : "r"(addr))

#define CP16(dst, src)                                                        \
    asm volatile("cp.async.cg.shared.global [%0], [%1], 16;\n"                \
                 :: "r"(dst), "l"(src))
#define CP_COMMIT() asm volatile("cp.async.commit_group;\n" ::: "memory")
#define CP_WAIT1()  asm volatile("cp.async.wait_group 1;\n" ::: "memory")

__device__ __forceinline__ void split2pack(float x, float y,
                                           uint32_t& hi, uint32_t& lo)
{
    __nv_bfloat16 hx = __float2bfloat16(x), hy = __float2bfloat16(y);
    __nv_bfloat16 lx = __float2bfloat16(x - __bfloat162float(hx));
    __nv_bfloat16 ly = __float2bfloat16(y - __bfloat162float(hy));
    __nv_bfloat162 th = __halves2bfloat162(hx, hy);
    __nv_bfloat162 tl = __halves2bfloat162(lx, ly);
    hi = *reinterpret_cast<uint32_t*>(&th);
    lo = *reinterpret_cast<uint32_t*>(&tl);
}

// ---------------- rope table (fp64 once, tiny) -----------------------------
__global__ void rope_table_kernel()
{
    int idx = blockIdx.x * blockDim.x + threadIdx.x;
    if (idx >= S_LEN * 64) return;
    int pos = idx >> 6;
    int i   = idx & 63;
    double inv = exp(-((double)(2 * i) / 128.0) * 9.210340371976184);
    double f   = (double)pos * inv;
    g_cs[idx] = make_float2((float)cos(f), (float)sin(f));
}

// ---------------- split fp32 -> bf16 hi/lo ---------------------------------
__global__ void split_kernel(const float* __restrict__ x,
                             __nv_bfloat16* __restrict__ hi,
                             __nv_bfloat16* __restrict__ lo, int n2)
{
    int i = blockIdx.x * blockDim.x + threadIdx.x;
    if (i >= n2) return;
    float2 v = ((const float2*)x)[i];
    __nv_bfloat16 h0 = __float2bfloat16(v.x);
    __nv_bfloat16 h1 = __float2bfloat16(v.y);
    __nv_bfloat16 l0 = __float2bfloat16(v.x - __bfloat162float(h0));
    __nv_bfloat16 l1 = __float2bfloat16(v.y - __bfloat162float(h1));
    ((__nv_bfloat162*)hi)[i] = __halves2bfloat162(h0, h1);
    ((__nv_bfloat162*)lo)[i] = __halves2bfloat162(l0, l1);
}

// ---------------- rope + split: fp32 in -> bf16 hi/lo out ------------------
__global__ void rope_split_kernel(const float* __restrict__ X,
                                  __nv_bfloat16* __restrict__ Xh,
                                  __nv_bfloat16* __restrict__ Xl, float scale)
{
    int idx = blockIdx.x * blockDim.x + threadIdx.x;
    if (idx >= TOKENS * NH * 64) return;
    int i  = idx & 63;
    int hh = (idx >> 6) & (NH - 1);
    int t  = idx >> 10;
    int pos = t & (S_LEN - 1);

    float2 cs = g_cs[pos * 64 + i];
    const float* p = X + (size_t)t * D_MODEL + hh * DH;
    float x1 = p[i];
    float x2 = p[i + 64];
    float y1 = (x1 * cs.x - x2 * cs.y) * scale;
    float y2 = (x2 * cs.x + x1 * cs.y) * scale;

    size_t o = (size_t)t * D_MODEL + hh * DH;
    __nv_bfloat16 h1 = __float2bfloat16(y1);
    __nv_bfloat16 h2 = __float2bfloat16(y2);
    Xh[o + i]      = h1;
    Xl[o + i]      = __float2bfloat16(y1 - __bfloat162float(h1));
    Xh[o + i + 64] = h2;
    Xl[o + i + 64] = __float2bfloat16(y2 - __bfloat162float(h2));
}

// ---------------- transpose + split: W[K][N] -> BT[N][K] bf16 hi/lo --------
__global__ void tsplit_kernel(const float* __restrict__ W,
                              __nv_bfloat16* __restrict__ hiT,
                              __nv_bfloat16* __restrict__ loT)
{
    __shared__ float tile[32][33];
    int tx = threadIdx.x, ty = threadIdx.y;
    int x0 = blockIdx.x * 32, y0 = blockIdx.y * 32;
    #pragma unroll
    for (int j = 0; j < 32; j += 8)
        tile[ty + j][tx] = W[(size_t)(y0 + ty + j) * D_MODEL + x0 + tx];
    __syncthreads();
    #pragma unroll
    for (int j = 0; j < 32; j += 8) {
        float v = tile[tx][ty + j];
        __nv_bfloat16 h = __float2bfloat16(v);
        __nv_bfloat16 l = __float2bfloat16(v - __bfloat162float(h));
        size_t o = (size_t)(x0 + ty + j) * D_MODEL + y0 + tx;
        hiT[o] = h;
        loT[o] = l;
    }
}

// ---------------- bf16x3 GEMM: cp.async 3-stage ring, 1 barrier/tile -------
#define TBM 128
#define TBN 128
#define TBK 32
#define TS  40                     // halves per row (padded)
#define TSZ (TBM * TS)
#define ASZ (TSZ * 2)              // bytes per array
#define STAGE_B (4 * ASZ)          // bytes per stage (40960)
#define GEMM_SMEM (3 * STAGE_B)    // 122880 B

__global__ void __launch_bounds__(256, 1) gemm_bf16x3_kernel(
    const __nv_bfloat16* __restrict__ Ah, const __nv_bfloat16* __restrict__ Al,
    const __nv_bfloat16* __restrict__ BTh, const __nv_bfloat16* __restrict__ BTl,
    float* __restrict__ C)
{
    const int K = D_MODEL, N = D_MODEL;
    extern __shared__ __nv_bfloat16 gsm[];
    const uint32_t cBase = (uint32_t)__cvta_generic_to_shared(gsm);

    const int t = threadIdx.x;
    const int bm = blockIdx.y, bn = blockIdx.x;
    const int warp = t >> 5, lane = t & 31;
    const int wm = warp >> 2;
    const int wn = warp & 3;
    const int g  = lane >> 2;
    const int tq = lane & 3;

    const uint32_t aoff = (uint32_t)(((wm * 64 + (lane & 15)) * TS + ((lane >> 4) * 8)) * 2);
    const uint32_t boff = (uint32_t)(((wn * 32 + (lane & 7) + ((lane >> 4) * 8)) * TS
                                     + (((lane >> 3) & 1) * 8)) * 2);
    const int lr = t >> 2;
    const int lc = (t & 3) * 8;

    float acc[4][4][4];
    #pragma unroll
    for (int a = 0; a < 4; a++)
        #pragma unroll
        for (int b = 0; b < 4; b++)
            #pragma unroll
            for (int c = 0; c < 4; c++) acc[a][b][c] = 0.0f;

    const int KT = K / TBK;   // 64

    auto load_stage = [&](int kt, int buf) {
        uint32_t sb = cBase + (uint32_t)buf * STAGE_B;
        int k0 = kt * TBK;
        #pragma unroll
        for (int rep = 0; rep < 2; rep++) {
            int r = lr + rep * 64;
            size_t ga = (size_t)(bm * TBM + r) * K + k0 + lc;
            size_t gb = (size_t)(bn * TBN + r) * K + k0 + lc;
            uint32_t ds = sb + (uint32_t)((r * TS + lc) * 2);
            CP16(ds,            Ah + ga);
            CP16(ds + ASZ,      Al + ga);
            CP16(ds + 2 * ASZ,  BTh + gb);
            CP16(ds + 3 * ASZ,  BTl + gb);
        }
    };

    load_stage(0, 0);
    CP_COMMIT();
    load_stage(1, 1);
    CP_COMMIT();

    int buf = 0, nbuf = 2;   // buf of kt; buffer for kt+2
    for (int kt = 0; kt < KT; kt++) {
        CP_WAIT1();          // group kt complete (kt+1 may remain pending)
        __syncthreads();     // all warps see stage kt; readers of buf(kt-1) done
        if (kt + 2 < KT) load_stage(kt + 2, nbuf);
        CP_COMMIT();         // empty group in tail keeps wait arithmetic uniform

        const uint32_t sb = cBase + (uint32_t)buf * STAGE_B;
        #pragma unroll
        for (int ks = 0; ks < 2; ks++) {
            const uint32_t kofs = ks * 32;
            uint32_t fah[4][4], fal[4][4], fbh[4][2], fbl[4][2];
            #pragma unroll
            for (int mf = 0; mf < 4; mf++) {
                uint32_t ad = sb + aoff + mf * (16 * TS * 2) + kofs;
                LDSM_X4(fah[mf][0], fah[mf][1], fah[mf][2], fah[mf][3], ad);
                LDSM_X4(fal[mf][0], fal[mf][1], fal[mf][2], fal[mf][3], ad + ASZ);
            }
            #pragma unroll
            for (int p = 0; p < 2; p++) {
                uint32_t bd = sb + 2 * ASZ + boff + p * (16 * TS * 2) + kofs;
                LDSM_X4(fbh[2*p][0], fbh[2*p][1], fbh[2*p+1][0], fbh[2*p+1][1], bd);
                LDSM_X4(fbl[2*p][0], fbl[2*p][1], fbl[2*p+1][0], fbl[2*p+1][1], bd + ASZ);
            }
            #pragma unroll
            for (int mf = 0; mf < 4; mf++)
                #pragma unroll
                for (int nf = 0; nf < 4; nf++) {
                    MMA16816(acc[mf][nf], fah[mf], fbh[nf]);
                    MMA16816(acc[mf][nf], fah[mf], fbl[nf]);
                    MMA16816(acc[mf][nf], fal[mf], fbh[nf]);
                }
        }
        buf = (buf + 1) % 3;
        nbuf = (nbuf + 1) % 3;
    }

    #pragma unroll
    for (int mf = 0; mf < 4; mf++) {
        int row = bm * TBM + wm * 64 + mf * 16 + g;
        #pragma unroll
        for (int nf = 0; nf < 4; nf++) {
            int col = bn * TBN + wn * 32 + nf * 8 + tq * 2;
            *(float2*)&C[(size_t)row * N + col] =
                make_float2(acc[mf][nf][0], acc[mf][nf][1]);
            *(float2*)&C[(size_t)(row + 8) * N + col] =
                make_float2(acc[mf][nf][2], acc[mf][nf][3]);
        }
    }
}

// ---------------- tensor-core flash attention (bf16x3, causal, BQ=128) -----
#define AT_SD 136          // smem stride (halves): 272B, LDSM conflict-free
#define ATT_SMEM ((2 * 128 + 4 * 64) * AT_SD * 2)   // 139264 B

__global__ void __launch_bounds__(256) attn_tc_kernel(
    const __nv_bfloat16* __restrict__ Qh, const __nv_bfloat16* __restrict__ Ql,
    const __nv_bfloat16* __restrict__ Kh, const __nv_bfloat16* __restrict__ Kl,
    const __nv_bfloat16* __restrict__ Vh, const __nv_bfloat16* __restrict__ Vl,
    float* __restrict__ O)
{
    const int b = blockIdx.z, h = blockIdx.y, qb = blockIdx.x;   // qb: 128-row tile
    const int tid = threadIdx.x, warp = tid >> 5, lane = tid & 31;
    const int g = lane >> 2, tq = lane & 3;

    extern __shared__ __nv_bfloat16 sh[];
    __nv_bfloat16* sQh = sh;
    __nv_bfloat16* sQl = sQh + 128 * AT_SD;
    __nv_bfloat16* sKh = sQl + 128 * AT_SD;
    __nv_bfloat16* sKl = sKh + 64 * AT_SD;
    __nv_bfloat16* sVh = sKl + 64 * AT_SD;
    __nv_bfloat16* sVl = sVh + 64 * AT_SD;

    const size_t base = ((size_t)b * S_LEN) * D_MODEL + (size_t)h * DH;

    // stage Q tile (128 rows x 128 dh)
    for (int i = tid; i < 128 * 16; i += 256) {
        int r = i >> 4, c = (i & 15) << 3;
        size_t src = base + (size_t)(qb * 128 + r) * D_MODEL + c;
        *(uint4*)&sQh[r * AT_SD + c] = *(const uint4*)(Qh + src);
        *(uint4*)&sQl[r * AT_SD + c] = *(const uint4*)(Ql + src);
    }

    float o[16][4];
    #pragma unroll
    for (int nf = 0; nf < 16; nf++)
        #pragma unroll
        for (int c = 0; c < 4; c++) o[nf][c] = 0.0f;
    float mr0 = -INFINITY, mr1 = -INFINITY, lr0 = 0.0f, lr1 = 0.0f;

    const uint32_t cQh = (uint32_t)__cvta_generic_to_shared(sQh);
    const uint32_t cQl = (uint32_t)__cvta_generic_to_shared(sQl);
    const uint32_t cKh = (uint32_t)__cvta_generic_to_shared(sKh);
    const uint32_t cKl = (uint32_t)__cvta_generic_to_shared(sKl);
    const uint32_t cVh = (uint32_t)__cvta_generic_to_shared(sVh);
    const uint32_t cVl = (uint32_t)__cvta_generic_to_shared(sVl);
    const uint32_t aoff  = (uint32_t)(((warp * 16 + (lane & 15)) * AT_SD + ((lane >> 4) * 8)) * 2);
    const uint32_t boffK = (uint32_t)((((lane & 7) + ((lane >> 4) * 8)) * AT_SD
                                      + (((lane >> 3) & 1) * 8)) * 2);
    const uint32_t boffVt = (uint32_t)(((lane & 15) * AT_SD + ((lane >> 4) * 8)) * 2);

    const int kbmax = 2 * qb + 1;
    for (int kb = 0; kb <= kbmax; kb++) {
        __syncthreads();   // prior iter's smem reads done (covers Q store, iter 0)
        for (int i = tid; i < 64 * 16; i += 256) {
            int r = i >> 4, c = (i & 15) << 3;
            size_t src = base + (size_t)(kb * 64 + r) * D_MODEL + c;
            *(uint4*)&sKh[r * AT_SD + c] = *(const uint4*)(Kh + src);
            *(uint4*)&sKl[r * AT_SD + c] = *(const uint4*)(Kl + src);
            *(uint4*)&sVh[r * AT_SD + c] = *(const uint4*)(Vh + src);
            *(uint4*)&sVl[r * AT_SD + c] = *(const uint4*)(Vl + src);
        }
        __syncthreads();

        // ---- S = Q K^T (16 x 64 per warp), bf16x3 ----
        float s[8][4];
        #pragma unroll
        for (int tt = 0; tt < 8; tt++)
            #pragma unroll
            for (int c = 0; c < 4; c++) s[tt][c] = 0.0f;

        #pragma unroll
        for (int ks = 0; ks < 8; ks++) {
            uint32_t qh[4], ql[4];
            LDSM_X4(qh[0], qh[1], qh[2], qh[3], cQh + aoff + ks * 32);
            LDSM_X4(ql[0], ql[1], ql[2], ql[3], cQl + aoff + ks * 32);
            #pragma unroll
            for (int p = 0; p < 4; p++) {
                uint32_t kh[4], kl[4];
                uint32_t bd = boffK + p * (16 * AT_SD * 2) + ks * 32;
                LDSM_X4(kh[0], kh[1], kh[2], kh[3], cKh + bd);
                LDSM_X4(kl[0], kl[1], kl[2], kl[3], cKl + bd);
                uint32_t bh0[2] = {kh[0], kh[1]}, bh1[2] = {kh[2], kh[3]};
                uint32_t bl0[2] = {kl[0], kl[1]}, bl1[2] = {kl[2], kl[3]};
                MMA16816(s[2*p],     qh, bh0);
                MMA16816(s[2*p],     ql, bh0);
                MMA16816(s[2*p],     qh, bl0);
                MMA16816(s[2*p + 1], qh, bh1);
                MMA16816(s[2*p + 1], ql, bh1);
                MMA16816(s[2*p + 1], qh, bl1);
            }
        }

        if (kb >= 2 * qb) {   // only the last two kv-blocks can cross the diagonal
            int rg0 = qb * 128 + warp * 16 + g;
            int rg1 = rg0 + 8;
            #pragma unroll
            for (int tt = 0; tt < 8; tt++) {
                int cg = kb * 64 + tt * 8 + tq * 2;
                if (cg     > rg0) s[tt][0] = -INFINITY;
                if (cg + 1 > rg0) s[tt][1] = -INFINITY;
                if (cg     > rg1) s[tt][2] = -INFINITY;
                if (cg + 1 > rg1) s[tt][3] = -INFINITY;
            }
        }

        // ---- online softmax (rows g, g+8) ----
        float mx0 = -INFINITY, mx1 = -INFINITY;
        #pragma unroll
        for (int tt = 0; tt < 8; tt++) {
            mx0 = fmaxf(mx0, fmaxf(s[tt][0], s[tt][1]));
            mx1 = fmaxf(mx1, fmaxf(s[tt][2], s[tt][3]));
        }
        mx0 = fmaxf(mx0, __shfl_xor_sync(0xffffffffu, mx0, 1));
        mx0 = fmaxf(mx0, __shfl_xor_sync(0xffffffffu, mx0, 2));
        mx1 = fmaxf(mx1, __shfl_xor_sync(0xffffffffu, mx1, 1));
        mx1 = fmaxf(mx1, __shfl_xor_sync(0xffffffffu, mx1, 2));

        float mn0 = fmaxf(mr0, mx0), mn1 = fmaxf(mr1, mx1);
        float al0 = __expf(mr0 - mn0), al1 = __expf(mr1 - mn1);
        float sum0 = 0.0f, sum1 = 0.0f;
        #pragma unroll
        for (int tt = 0; tt < 8; tt++) {
            s[tt][0] = __expf(s[tt][0] - mn0);
            s[tt][1] = __expf(s[tt][1] - mn0);
            s[tt][2] = __expf(s[tt][2] - mn1);
            s[tt][3] = __expf(s[tt][3] - mn1);
            sum0 += s[tt][0] + s[tt][1];
            sum1 += s[tt][2] + s[tt][3];
        }
        sum0 += __shfl_xor_sync(0xffffffffu, sum0, 1);
        sum0 += __shfl_xor_sync(0xffffffffu, sum0, 2);
        sum1 += __shfl_xor_sync(0xffffffffu, sum1, 1);
        sum1 += __shfl_xor_sync(0xffffffffu, sum1, 2);
        lr0 = lr0 * al0 + sum0;
        lr1 = lr1 * al1 + sum1;
        mr0 = mn0;
        mr1 = mn1;
        #pragma unroll
        for (int nf = 0; nf < 16; nf++) {
            o[nf][0] *= al0; o[nf][1] *= al0;
            o[nf][2] *= al1; o[nf][3] *= al1;
        }

        // ---- O += P V  (P from registers; V via trans ldmatrix) ----
        #pragma unroll
        for (int j = 0; j < 4; j++) {
            uint32_t ph[4], pl[4];
            split2pack(s[2*j][0],     s[2*j][1],     ph[0], pl[0]);
            split2pack(s[2*j][2],     s[2*j][3],     ph[1], pl[1]);
            split2pack(s[2*j + 1][0], s[2*j + 1][1], ph[2], pl[2]);
            split2pack(s[2*j + 1][2], s[2*j + 1][3], ph[3], pl[3]);
            #pragma unroll
            for (int dtile = 0; dtile < 8; dtile++) {
                uint32_t vh4[4], vl4[4];
                uint32_t bd = boffVt + (uint32_t)((j * 16 * AT_SD + dtile * 16) * 2);
                LDSM_X4_T(vh4[0], vh4[1], vh4[2], vh4[3], cVh + bd);
                LDSM_X4_T(vl4[0], vl4[1], vl4[2], vl4[3], cVl + bd);
                uint32_t bh0[2] = {vh4[0], vh4[1]}, bh1[2] = {vh4[2], vh4[3]};
                uint32_t bl0[2] = {vl4[0], vl4[1]}, bl1[2] = {vl4[2], vl4[3]};
                MMA16816(o[2*dtile],     ph, bh0);
                MMA16816(o[2*dtile],     pl, bh0);
                MMA16816(o[2*dtile],     ph, bl0);
                MMA16816(o[2*dtile + 1], ph, bh1);
                MMA16816(o[2*dtile + 1], pl, bh1);
                MMA16816(o[2*dtile + 1], ph, bl1);
            }
        }
    }

    // epilogue: o[2*dtile + u] -> dh cols dtile*16 + u*8 + tq*2
    float inv0 = 1.0f / lr0, inv1 = 1.0f / lr1;
    int r0 = qb * 128 + warp * 16 + g;
    #pragma unroll
    for (int dtile = 0; dtile < 8; dtile++) {
        #pragma unroll
        for (int u = 0; u < 2; u++) {
            int nf = 2 * dtile + u;
            int c = dtile * 16 + u * 8 + tq * 2;
            *(float2*)&O[base + (size_t)r0 * D_MODEL + c] =
                make_float2(o[nf][0] * inv0, o[nf][1] * inv0);
            *(float2*)&O[base + (size_t)(r0 + 8) * D_MODEL + c] =
                make_float2(o[nf][2] * inv1, o[nf][3] * inv1);
        }
    }
}

// ---------------- launch ----------------------------------------------------
extern "C" void kernel_launch(void* const* d_in, const int* in_sizes, int n_in,
                              void* d_out, int out_size)
{
    (void)in_sizes; (void)n_in; (void)out_size;
    const float* hidden = (const float*)d_in[0];
    const float* Wq = (const float*)d_in[3];
    const float* Wk = (const float*)d_in[4];
    const float* Wv = (const float*)d_in[5];
    const float* Wo = (const float*)d_in[6];
    float* out = (float*)d_out;

    float *Qp, *Kp, *Vp, *Op;
    __nv_bfloat16 *Ahp, *Alp, *Bhp, *Blp;
    __nv_bfloat16 *Qhp, *Qlp, *Khp, *Klp, *Vhp, *Vlp;
    cudaGetSymbolAddress((void**)&Qp, g_Q);
    cudaGetSymbolAddress((void**)&Kp, g_K);
    cudaGetSymbolAddress((void**)&Vp, g_V);
    cudaGetSymbolAddress((void**)&Op, g_O);
    cudaGetSymbolAddress((void**)&Ahp, g_Ah);
    cudaGetSymbolAddress((void**)&Alp, g_Al);
    cudaGetSymbolAddress((void**)&Bhp, g_Bh);
    cudaGetSymbolAddress((void**)&Blp, g_Bl);
    cudaGetSymbolAddress((void**)&Qhp, g_Qh);
    cudaGetSymbolAddress((void**)&Qlp, g_Ql);
    cudaGetSymbolAddress((void**)&Khp, g_Kh);
    cudaGetSymbolAddress((void**)&Klp, g_Kl);
    cudaGetSymbolAddress((void**)&Vhp, g_Vh);
    cudaGetSymbolAddress((void**)&Vlp, g_Vl);

    rope_table_kernel<<<(S_LEN * 64 + 255) / 256, 256>>>();

    int n2 = TOKENS * D_MODEL / 2;
    split_kernel<<<(n2 + 255) / 256, 256>>>(hidden, Ahp, Alp, n2);

    dim3 tgrid(D_MODEL / 32, D_MODEL / 32);
    dim3 tblk(32, 8);
    dim3 ggrid(D_MODEL / TBN, TOKENS / TBM);

    cudaFuncSetAttribute(gemm_bf16x3_kernel,
                         cudaFuncAttributeMaxDynamicSharedMemorySize, GEMM_SMEM);

    tsplit_kernel<<<tgrid, tblk>>>(Wq, Bhp, Blp);
    gemm_bf16x3_kernel<<<ggrid, 256, GEMM_SMEM>>>(Ahp, Alp, Bhp, Blp, Qp);
    tsplit_kernel<<<tgrid, tblk>>>(Wk, Bhp, Blp);
    gemm_bf16x3_kernel<<<ggrid, 256, GEMM_SMEM>>>(Ahp, Alp, Bhp, Blp, Kp);
    tsplit_kernel<<<tgrid, tblk>>>(Wv, Bhp, Blp);
    gemm_bf16x3_kernel<<<ggrid, 256, GEMM_SMEM>>>(Ahp, Alp, Bhp, Blp, Vp);

    int nrope = TOKENS * NH * 64;
    rope_split_kernel<<<(nrope + 255) / 256, 256>>>(Qp, Qhp, Qlp, 0.08838834764831845f);
    rope_split_kernel<<<(nrope + 255) / 256, 256>>>(Kp, Khp, Klp, 1.0f);
    split_kernel<<<(n2 + 255) / 256, 256>>>(Vp, Vhp, Vlp, n2);

    cudaFuncSetAttribute(attn_tc_kernel,
                         cudaFuncAttributeMaxDynamicSharedMemorySize, ATT_SMEM);
    attn_tc_kernel<<<dim3(S_LEN / 128, NH, BATCH), 256, ATT_SMEM>>>(
        Qhp, Qlp, Khp, Klp, Vhp, Vlp, Op);

    split_kernel<<<(n2 + 255) / 256, 256>>>(Op, Ahp, Alp, n2);
    tsplit_kernel<<<tgrid, tblk>>>(Wo, Bhp, Blp);
    gemm_bf16x3_kernel<<<ggrid, 256, GEMM_SMEM>>>(Ahp, Alp, Bhp, Blp, out);
}

// round 14
// speedup vs baseline: 1.0746x; 1.0746x over previous
#include <cuda_runtime.h>
#include <cuda_bf16.h>
#include <cstdint>
#include <math.h>

#define S_LEN   2048
#define D_MODEL 2048
#define NH      16
#define DH      128
#define BATCH   2
#define TOKENS  (BATCH * S_LEN)   // 4096

// ---------------- scratch (device globals: allocation-free) ----------------
__device__ float g_Q[TOKENS * D_MODEL];
__device__ float g_K[TOKENS * D_MODEL];
__device__ float g_V[TOKENS * D_MODEL];
__device__ float g_O[TOKENS * D_MODEL];
__device__ __nv_bfloat16 g_Ah[TOKENS * D_MODEL];
__device__ __nv_bfloat16 g_Al[TOKENS * D_MODEL];
__device__ __nv_bfloat16 g_Bh[D_MODEL * D_MODEL];
__device__ __nv_bfloat16 g_Bl[D_MODEL * D_MODEL];
__device__ __nv_bfloat16 g_Qh[TOKENS * D_MODEL];
__device__ __nv_bfloat16 g_Ql[TOKENS * D_MODEL];
__device__ __nv_bfloat16 g_Kh[TOKENS * D_MODEL];
__device__ __nv_bfloat16 g_Kl[TOKENS * D_MODEL];
__device__ __nv_bfloat16 g_Vh[TOKENS * D_MODEL];
__device__ __nv_bfloat16 g_Vl[TOKENS * D_MODEL];
__device__ float2 g_cs[S_LEN * 64];

// ---------------- common asm helpers ---------------------------------------
#define MMA16816(d, a, b)                                                     \
    asm volatile(                                                             \
        "mma.sync.aligned.m16n8k16.row.col.f32.bf16.bf16.f32 "                \
        "{%0,%1,%2,%3},{%4,%5,%6,%7},{%8,%9},{%0,%1,%2,%3};\n"                \
        : "+f"(d[0]), "+f"(d[1]), "+f"(d[2]), "+f"(d[3])                      \
        : "r"(a[0]), "r"(a[1]), "r"(a[2]), "r"(a[3]), "r"(b[0]), "r"(b[1]))

#define LDSM_X4(d0, d1, d2, d3, addr)                                         \
    asm volatile("ldmatrix.sync.aligned.m8n8.x4.shared.b16 {%0,%1,%2,%3}, [%4];" \
                 : "=r"(d0), "=r"(d1), "=r"(d2), "=r"(d3) : "r"(addr))

#define LDSM_X4_T(d0, d1, d2, d3, addr)                                       \
    asm volatile("ldmatrix.sync.aligned.m8n8.x4.trans.shared.b16 {%0,%1,%2,%3}, [%4];" \
                 : "=r"(d0), "=r"(d1), "=r"(d2), "=r"(d3) : "r"(addr))

#define CP16(dst, src)                                                        \
    asm volatile("cp.async.cg.shared.global [%0], [%1], 16;\n"                \
                 :: "r"(dst), "l"(src))
#define CP_COMMIT() asm volatile("cp.async.commit_group;\n" ::: "memory")
#define CP_WAIT0()  asm volatile("cp.async.wait_group 0;\n" ::: "memory")

__device__ __forceinline__ void split2pack(float x, float y,
                                           uint32_t& hi, uint32_t& lo)
{
    __nv_bfloat16 hx = __float2bfloat16(x), hy = __float2bfloat16(y);
    __nv_bfloat16 lx = __float2bfloat16(x - __bfloat162float(hx));
    __nv_bfloat16 ly = __float2bfloat16(y - __bfloat162float(hy));
    __nv_bfloat162 th = __halves2bfloat162(hx, hy);
    __nv_bfloat162 tl = __halves2bfloat162(lx, ly);
    hi = *reinterpret_cast<uint32_t*>(&th);
    lo = *reinterpret_cast<uint32_t*>(&tl);
}

// ---------------- rope table (fp64 once, tiny) -----------------------------
__global__ void rope_table_kernel()
{
    int idx = blockIdx.x * blockDim.x + threadIdx.x;
    if (idx >= S_LEN * 64) return;
    int pos = idx >> 6;
    int i   = idx & 63;
    double inv = exp(-((double)(2 * i) / 128.0) * 9.210340371976184);
    double f   = (double)pos * inv;
    g_cs[idx] = make_float2((float)cos(f), (float)sin(f));
}

// ---------------- split fp32 -> bf16 hi/lo ---------------------------------
__global__ void split_kernel(const float* __restrict__ x,
                             __nv_bfloat16* __restrict__ hi,
                             __nv_bfloat16* __restrict__ lo, int n2)
{
    int i = blockIdx.x * blockDim.x + threadIdx.x;
    if (i >= n2) return;
    float2 v = ((const float2*)x)[i];
    __nv_bfloat16 h0 = __float2bfloat16(v.x);
    __nv_bfloat16 h1 = __float2bfloat16(v.y);
    __nv_bfloat16 l0 = __float2bfloat16(v.x - __bfloat162float(h0));
    __nv_bfloat16 l1 = __float2bfloat16(v.y - __bfloat162float(h1));
    ((__nv_bfloat162*)hi)[i] = __halves2bfloat162(h0, h1);
    ((__nv_bfloat162*)lo)[i] = __halves2bfloat162(l0, l1);
}

// ---------------- rope + split: fp32 in -> bf16 hi/lo out ------------------
__global__ void rope_split_kernel(const float* __restrict__ X,
                                  __nv_bfloat16* __restrict__ Xh,
                                  __nv_bfloat16* __restrict__ Xl, float scale)
{
    int idx = blockIdx.x * blockDim.x + threadIdx.x;
    if (idx >= TOKENS * NH * 64) return;
    int i  = idx & 63;
    int hh = (idx >> 6) & (NH - 1);
    int t  = idx >> 10;
    int pos = t & (S_LEN - 1);

    float2 cs = g_cs[pos * 64 + i];
    const float* p = X + (size_t)t * D_MODEL + hh * DH;
    float x1 = p[i];
    float x2 = p[i + 64];
    float y1 = (x1 * cs.x - x2 * cs.y) * scale;
    float y2 = (x2 * cs.x + x1 * cs.y) * scale;

    size_t o = (size_t)t * D_MODEL + hh * DH;
    __nv_bfloat16 h1 = __float2bfloat16(y1);
    __nv_bfloat16 h2 = __float2bfloat16(y2);
    Xh[o + i]      = h1;
    Xl[o + i]      = __float2bfloat16(y1 - __bfloat162float(h1));
    Xh[o + i + 64] = h2;
    Xl[o + i + 64] = __float2bfloat16(y2 - __bfloat162float(h2));
}

// ---------------- transpose + split: W[K][N] -> BT[N][K] bf16 hi/lo --------
__global__ void tsplit_kernel(const float* __restrict__ W,
                              __nv_bfloat16* __restrict__ hiT,
                              __nv_bfloat16* __restrict__ loT)
{
    __shared__ float tile[32][33];
    int tx = threadIdx.x, ty = threadIdx.y;
    int x0 = blockIdx.x * 32, y0 = blockIdx.y * 32;
    #pragma unroll
    for (int j = 0; j < 32; j += 8)
        tile[ty + j][tx] = W[(size_t)(y0 + ty + j) * D_MODEL + x0 + tx];
    __syncthreads();
    #pragma unroll
    for (int j = 0; j < 32; j += 8) {
        float v = tile[tx][ty + j];
        __nv_bfloat16 h = __float2bfloat16(v);
        __nv_bfloat16 l = __float2bfloat16(v - __bfloat162float(h));
        size_t o = (size_t)(x0 + ty + j) * D_MODEL + y0 + tx;
        hiT[o] = h;
        loT[o] = l;
    }
}

// ---------------- bf16x3 GEMM: 2-stage cp.async, 1 barrier/tile ------------
#define TBM 128
#define TBN 128
#define TBK 32
#define TS  40                     // halves per row (padded)
#define TSZ (TBM * TS)
#define ASZ (TSZ * 2)              // bytes per array
#define STAGE_B (4 * ASZ)          // bytes per stage (40960)
#define GEMM_SMEM (2 * STAGE_B)    // 81920 B -> 2 CTA/SM

__global__ void __launch_bounds__(256, 2) gemm_bf16x3_kernel(
    const __nv_bfloat16* __restrict__ Ah, const __nv_bfloat16* __restrict__ Al,
    const __nv_bfloat16* __restrict__ BTh, const __nv_bfloat16* __restrict__ BTl,
    float* __restrict__ C)
{
    const int K = D_MODEL, N = D_MODEL;
    extern __shared__ __nv_bfloat16 gsm[];
    const uint32_t cBase = (uint32_t)__cvta_generic_to_shared(gsm);

    const int t = threadIdx.x;
    const int bm = blockIdx.y, bn = blockIdx.x;
    const int warp = t >> 5, lane = t & 31;
    const int wm = warp >> 2;
    const int wn = warp & 3;
    const int g  = lane >> 2;
    const int tq = lane & 3;

    const uint32_t aoff = (uint32_t)(((wm * 64 + (lane & 15)) * TS + ((lane >> 4) * 8)) * 2);
    const uint32_t boff = (uint32_t)(((wn * 32 + (lane & 7) + ((lane >> 4) * 8)) * TS
                                     + (((lane >> 3) & 1) * 8)) * 2);
    const int lr = t >> 2;
    const int lc = (t & 3) * 8;

    float acc[4][4][4];
    #pragma unroll
    for (int a = 0; a < 4; a++)
        #pragma unroll
        for (int b = 0; b < 4; b++)
            #pragma unroll
            for (int c = 0; c < 4; c++) acc[a][b][c] = 0.0f;

    const int KT = K / TBK;   // 64

    auto load_stage = [&](int kt, int buf) {
        uint32_t sb = cBase + (uint32_t)buf * STAGE_B;
        int k0 = kt * TBK;
        #pragma unroll
        for (int rep = 0; rep < 2; rep++) {
            int r = lr + rep * 64;
            size_t ga = (size_t)(bm * TBM + r) * K + k0 + lc;
            size_t gb = (size_t)(bn * TBN + r) * K + k0 + lc;
            uint32_t ds = sb + (uint32_t)((r * TS + lc) * 2);
            CP16(ds,            Ah + ga);
            CP16(ds + ASZ,      Al + ga);
            CP16(ds + 2 * ASZ,  BTh + gb);
            CP16(ds + 3 * ASZ,  BTl + gb);
        }
    };

    load_stage(0, 0);
    CP_COMMIT();

    for (int kt = 0; kt < KT; kt++) {
        // wait for stage kt's data to arrive (only pending group)
        CP_WAIT0();
        // ONE barrier: (a) makes stage kt visible to all warps,
        //              (b) fences all readers of buf (kt-1)&1 = (kt+1)&1
        __syncthreads();
        if (kt + 1 < KT) {
            load_stage(kt + 1, (kt + 1) & 1);  // overlaps compute of kt
            CP_COMMIT();
        }

        const uint32_t sb = cBase + (uint32_t)(kt & 1) * STAGE_B;
        #pragma unroll
        for (int ks = 0; ks < 2; ks++) {
            const uint32_t kofs = ks * 32;
            uint32_t fah[4][4], fal[4][4], fbh[4][2], fbl[4][2];
            #pragma unroll
            for (int mf = 0; mf < 4; mf++) {
                uint32_t ad = sb + aoff + mf * (16 * TS * 2) + kofs;
                LDSM_X4(fah[mf][0], fah[mf][1], fah[mf][2], fah[mf][3], ad);
                LDSM_X4(fal[mf][0], fal[mf][1], fal[mf][2], fal[mf][3], ad + ASZ);
            }
            #pragma unroll
            for (int p = 0; p < 2; p++) {
                uint32_t bd = sb + 2 * ASZ + boff + p * (16 * TS * 2) + kofs;
                LDSM_X4(fbh[2*p][0], fbh[2*p][1], fbh[2*p+1][0], fbh[2*p+1][1], bd);
                LDSM_X4(fbl[2*p][0], fbl[2*p][1], fbl[2*p+1][0], fbl[2*p+1][1], bd + ASZ);
            }
            #pragma unroll
            for (int mf = 0; mf < 4; mf++)
                #pragma unroll
                for (int nf = 0; nf < 4; nf++) {
                    MMA16816(acc[mf][nf], fah[mf], fbh[nf]);
                    MMA16816(acc[mf][nf], fah[mf], fbl[nf]);
                    MMA16816(acc[mf][nf], fal[mf], fbh[nf]);
                }
        }
    }

    #pragma unroll
    for (int mf = 0; mf < 4; mf++) {
        int row = bm * TBM + wm * 64 + mf * 16 + g;
        #pragma unroll
        for (int nf = 0; nf < 4; nf++) {
            int col = bn * TBN + wn * 32 + nf * 8 + tq * 2;
            *(float2*)&C[(size_t)row * N + col] =
                make_float2(acc[mf][nf][0], acc[mf][nf][1]);
            *(float2*)&C[(size_t)(row + 8) * N + col] =
                make_float2(acc[mf][nf][2], acc[mf][nf][3]);
        }
    }
}

// ---------------- tensor-core flash attention (bf16x3, causal, BQ=64) ------
#define AT_SD 136          // smem stride (halves): 272B, LDSM conflict-free
#define AT_TILE (64 * AT_SD)
#define ATT_SMEM (6 * AT_TILE * 2)   // 104448 B

__global__ void __launch_bounds__(128) attn_tc_kernel(
    const __nv_bfloat16* __restrict__ Qh, const __nv_bfloat16* __restrict__ Ql,
    const __nv_bfloat16* __restrict__ Kh, const __nv_bfloat16* __restrict__ Kl,
    const __nv_bfloat16* __restrict__ Vh, const __nv_bfloat16* __restrict__ Vl,
    float* __restrict__ O)
{
    const int b = blockIdx.z, h = blockIdx.y, qb = blockIdx.x;
    const int tid = threadIdx.x, warp = tid >> 5, lane = tid & 31;
    const int g = lane >> 2, tq = lane & 3;

    extern __shared__ __nv_bfloat16 sh[];
    __nv_bfloat16* sQh = sh;
    __nv_bfloat16* sQl = sQh + AT_TILE;
    __nv_bfloat16* sKh = sQl + AT_TILE;
    __nv_bfloat16* sKl = sKh + AT_TILE;
    __nv_bfloat16* sVh = sKl + AT_TILE;
    __nv_bfloat16* sVl = sVh + AT_TILE;

    const size_t base = ((size_t)b * S_LEN) * D_MODEL + (size_t)h * DH;

    for (int i = tid; i < 64 * 16; i += 128) {
        int r = i >> 4, c = (i & 15) << 3;
        size_t src = base + (size_t)(qb * 64 + r) * D_MODEL + c;
        *(uint4*)&sQh[r * AT_SD + c] = *(const uint4*)(Qh + src);
        *(uint4*)&sQl[r * AT_SD + c] = *(const uint4*)(Ql + src);
    }

    float o[16][4];
    #pragma unroll
    for (int nf = 0; nf < 16; nf++)
        #pragma unroll
        for (int c = 0; c < 4; c++) o[nf][c] = 0.0f;
    float mr0 = -INFINITY, mr1 = -INFINITY, lr0 = 0.0f, lr1 = 0.0f;

    const uint32_t cQh = (uint32_t)__cvta_generic_to_shared(sQh);
    const uint32_t cQl = (uint32_t)__cvta_generic_to_shared(sQl);
    const uint32_t cKh = (uint32_t)__cvta_generic_to_shared(sKh);
    const uint32_t cKl = (uint32_t)__cvta_generic_to_shared(sKl);
    const uint32_t cVh = (uint32_t)__cvta_generic_to_shared(sVh);
    const uint32_t cVl = (uint32_t)__cvta_generic_to_shared(sVl);
    const uint32_t aoff  = (uint32_t)(((warp * 16 + (lane & 15)) * AT_SD + ((lane >> 4) * 8)) * 2);
    const uint32_t boffK = (uint32_t)((((lane & 7) + ((lane >> 4) * 8)) * AT_SD
                                      + (((lane >> 3) & 1) * 8)) * 2);
    const uint32_t boffVt = (uint32_t)(((lane & 15) * AT_SD + ((lane >> 4) * 8)) * 2);

    for (int kb = 0; kb <= qb; kb++) {
        __syncthreads();
        for (int i = tid; i < 64 * 16; i += 128) {
            int r = i >> 4, c = (i & 15) << 3;
            size_t src = base + (size_t)(kb * 64 + r) * D_MODEL + c;
            *(uint4*)&sKh[r * AT_SD + c] = *(const uint4*)(Kh + src);
            *(uint4*)&sKl[r * AT_SD + c] = *(const uint4*)(Kl + src);
            *(uint4*)&sVh[r * AT_SD + c] = *(const uint4*)(Vh + src);
            *(uint4*)&sVl[r * AT_SD + c] = *(const uint4*)(Vl + src);
        }
        __syncthreads();

        float s[8][4];
        #pragma unroll
        for (int tt = 0; tt < 8; tt++)
            #pragma unroll
            for (int c = 0; c < 4; c++) s[tt][c] = 0.0f;

        #pragma unroll
        for (int ks = 0; ks < 8; ks++) {
            uint32_t qh[4], ql[4];
            LDSM_X4(qh[0], qh[1], qh[2], qh[3], cQh + aoff + ks * 32);
            LDSM_X4(ql[0], ql[1], ql[2], ql[3], cQl + aoff + ks * 32);
            #pragma unroll
            for (int p = 0; p < 4; p++) {
                uint32_t kh[4], kl[4];
                uint32_t bd = boffK + p * (16 * AT_SD * 2) + ks * 32;
                LDSM_X4(kh[0], kh[1], kh[2], kh[3], cKh + bd);
                LDSM_X4(kl[0], kl[1], kl[2], kl[3], cKl + bd);
                uint32_t bh0[2] = {kh[0], kh[1]}, bh1[2] = {kh[2], kh[3]};
                uint32_t bl0[2] = {kl[0], kl[1]}, bl1[2] = {kl[2], kl[3]};
                MMA16816(s[2*p],     qh, bh0);
                MMA16816(s[2*p],     ql, bh0);
                MMA16816(s[2*p],     qh, bl0);
                MMA16816(s[2*p + 1], qh, bh1);
                MMA16816(s[2*p + 1], ql, bh1);
                MMA16816(s[2*p + 1], qh, bl1);
            }
        }

        if (kb == qb) {
            int r0 = warp * 16 + g, r1 = r0 + 8;
            #pragma unroll
            for (int tt = 0; tt < 8; tt++) {
                int c0 = tt * 8 + tq * 2;
                if (c0     > r0) s[tt][0] = -INFINITY;
                if (c0 + 1 > r0) s[tt][1] = -INFINITY;
                if (c0     > r1) s[tt][2] = -INFINITY;
                if (c0 + 1 > r1) s[tt][3] = -INFINITY;
            }
        }

        float mx0 = -INFINITY, mx1 = -INFINITY;
        #pragma unroll
        for (int tt = 0; tt < 8; tt++) {
            mx0 = fmaxf(mx0, fmaxf(s[tt][0], s[tt][1]));
            mx1 = fmaxf(mx1, fmaxf(s[tt][2], s[tt][3]));
        }
        mx0 = fmaxf(mx0, __shfl_xor_sync(0xffffffffu, mx0, 1));
        mx0 = fmaxf(mx0, __shfl_xor_sync(0xffffffffu, mx0, 2));
        mx1 = fmaxf(mx1, __shfl_xor_sync(0xffffffffu, mx1, 1));
        mx1 = fmaxf(mx1, __shfl_xor_sync(0xffffffffu, mx1, 2));

        float mn0 = fmaxf(mr0, mx0), mn1 = fmaxf(mr1, mx1);
        float al0 = __expf(mr0 - mn0), al1 = __expf(mr1 - mn1);
        float sum0 = 0.0f, sum1 = 0.0f;
        #pragma unroll
        for (int tt = 0; tt < 8; tt++) {
            s[tt][0] = __expf(s[tt][0] - mn0);
            s[tt][1] = __expf(s[tt][1] - mn0);
            s[tt][2] = __expf(s[tt][2] - mn1);
            s[tt][3] = __expf(s[tt][3] - mn1);
            sum0 += s[tt][0] + s[tt][1];
            sum1 += s[tt][2] + s[tt][3];
        }
        sum0 += __shfl_xor_sync(0xffffffffu, sum0, 1);
        sum0 += __shfl_xor_sync(0xffffffffu, sum0, 2);
        sum1 += __shfl_xor_sync(0xffffffffu, sum1, 1);
        sum1 += __shfl_xor_sync(0xffffffffu, sum1, 2);
        lr0 = lr0 * al0 + sum0;
        lr1 = lr1 * al1 + sum1;
        mr0 = mn0;
        mr1 = mn1;
        #pragma unroll
        for (int nf = 0; nf < 16; nf++) {
            o[nf][0] *= al0; o[nf][1] *= al0;
            o[nf][2] *= al1; o[nf][3] *= al1;
        }

        #pragma unroll
        for (int j = 0; j < 4; j++) {
            uint32_t ph[4], pl[4];
            split2pack(s[2*j][0],     s[2*j][1],     ph[0], pl[0]);
            split2pack(s[2*j][2],     s[2*j][3],     ph[1], pl[1]);
            split2pack(s[2*j + 1][0], s[2*j + 1][1], ph[2], pl[2]);
            split2pack(s[2*j + 1][2], s[2*j + 1][3], ph[3], pl[3]);
            #pragma unroll
            for (int dtile = 0; dtile < 8; dtile++) {
                uint32_t vh4[4], vl4[4];
                uint32_t bd = boffVt + (uint32_t)((j * 16 * AT_SD + dtile * 16) * 2);
                LDSM_X4_T(vh4[0], vh4[1], vh4[2], vh4[3], cVh + bd);
                LDSM_X4_T(vl4[0], vl4[1], vl4[2], vl4[3], cVl + bd);
                uint32_t bh0[2] = {vh4[0], vh4[1]}, bh1[2] = {vh4[2], vh4[3]};
                uint32_t bl0[2] = {vl4[0], vl4[1]}, bl1[2] = {vl4[2], vl4[3]};
                MMA16816(o[2*dtile],     ph, bh0);
                MMA16816(o[2*dtile],     pl, bh0);
                MMA16816(o[2*dtile],     ph, bl0);
                MMA16816(o[2*dtile + 1], ph, bh1);
                MMA16816(o[2*dtile + 1], pl, bh1);
                MMA16816(o[2*dtile + 1], ph, bl1);
            }
        }
    }

    float inv0 = 1.0f / lr0, inv1 = 1.0f / lr1;
    int r0 = qb * 64 + warp * 16 + g;
    #pragma unroll
    for (int dtile = 0; dtile < 8; dtile++) {
        #pragma unroll
        for (int u = 0; u < 2; u++) {
            int nf = 2 * dtile + u;
            int c = dtile * 16 + u * 8 + tq * 2;
            *(float2*)&O[base + (size_t)r0 * D_MODEL + c] =
                make_float2(o[nf][0] * inv0, o[nf][1] * inv0);
            *(float2*)&O[base + (size_t)(r0 + 8) * D_MODEL + c] =
                make_float2(o[nf][2] * inv1, o[nf][3] * inv1);
        }
    }
}

// ---------------- launch ----------------------------------------------------
extern "C" void kernel_launch(void* const* d_in, const int* in_sizes, int n_in,
                              void* d_out, int out_size)
{
    (void)in_sizes; (void)n_in; (void)out_size;
    const float* hidden = (const float*)d_in[0];
    const float* Wq = (const float*)d_in[3];
    const float* Wk = (const float*)d_in[4];
    const float* Wv = (const float*)d_in[5];
    const float* Wo = (const float*)d_in[6];
    float* out = (float*)d_out;

    float *Qp, *Kp, *Vp, *Op;
    __nv_bfloat16 *Ahp, *Alp, *Bhp, *Blp;
    __nv_bfloat16 *Qhp, *Qlp, *Khp, *Klp, *Vhp, *Vlp;
    cudaGetSymbolAddress((void**)&Qp, g_Q);
    cudaGetSymbolAddress((void**)&Kp, g_K);
    cudaGetSymbolAddress((void**)&Vp, g_V);
    cudaGetSymbolAddress((void**)&Op, g_O);
    cudaGetSymbolAddress((void**)&Ahp, g_Ah);
    cudaGetSymbolAddress((void**)&Alp, g_Al);
    cudaGetSymbolAddress((void**)&Bhp, g_Bh);
    cudaGetSymbolAddress((void**)&Blp, g_Bl);
    cudaGetSymbolAddress((void**)&Qhp, g_Qh);
    cudaGetSymbolAddress((void**)&Qlp, g_Ql);
    cudaGetSymbolAddress((void**)&Khp, g_Kh);
    cudaGetSymbolAddress((void**)&Klp, g_Kl);
    cudaGetSymbolAddress((void**)&Vhp, g_Vh);
    cudaGetSymbolAddress((void**)&Vlp, g_Vl);

    rope_table_kernel<<<(S_LEN * 64 + 255) / 256, 256>>>();

    int n2 = TOKENS * D_MODEL / 2;
    split_kernel<<<(n2 + 255) / 256, 256>>>(hidden, Ahp, Alp, n2);

    dim3 tgrid(D_MODEL / 32, D_MODEL / 32);
    dim3 tblk(32, 8);
    dim3 ggrid(D_MODEL / TBN, TOKENS / TBM);

    cudaFuncSetAttribute(gemm_bf16x3_kernel,
                         cudaFuncAttributeMaxDynamicSharedMemorySize, GEMM_SMEM);

    tsplit_kernel<<<tgrid, tblk>>>(Wq, Bhp, Blp);
    gemm_bf16x3_kernel<<<ggrid, 256, GEMM_SMEM>>>(Ahp, Alp, Bhp, Blp, Qp);
    tsplit_kernel<<<tgrid, tblk>>>(Wk, Bhp, Blp);
    gemm_bf16x3_kernel<<<ggrid, 256, GEMM_SMEM>>>(Ahp, Alp, Bhp, Blp, Kp);
    tsplit_kernel<<<tgrid, tblk>>>(Wv, Bhp, Blp);
    gemm_bf16x3_kernel<<<ggrid, 256, GEMM_SMEM>>>(Ahp, Alp, Bhp, Blp, Vp);

    int nrope = TOKENS * NH * 64;
    rope_split_kernel<<<(nrope + 255) / 256, 256>>>(Qp, Qhp, Qlp, 0.08838834764831845f);
    rope_split_kernel<<<(nrope + 255) / 256, 256>>>(Kp, Khp, Klp, 1.0f);
    split_kernel<<<(n2 + 255) / 256, 256>>>(Vp, Vhp, Vlp, n2);

    cudaFuncSetAttribute(attn_tc_kernel,
                         cudaFuncAttributeMaxDynamicSharedMemorySize, ATT_SMEM);
    attn_tc_kernel<<<dim3(S_LEN / 64, NH, BATCH), 128, ATT_SMEM>>>(
        Qhp, Qlp, Khp, Klp, Vhp, Vlp, Op);

    split_kernel<<<(n2 + 255) / 256, 256>>>(Op, Ahp, Alp, n2);
    tsplit_kernel<<<tgrid, tblk>>>(Wo, Bhp, Blp);
    gemm_bf16x3_kernel<<<ggrid, 256, GEMM_SMEM>>>(Ahp, Alp, Bhp, Blp, out);
}

// round 15
// speedup vs baseline: 1.3822x; 1.2862x over previous
#include <cuda_runtime.h>
#include <cuda_bf16.h>
#include <cuda_fp16.h>
#include <cstdint>
#include <math.h>

#define S_LEN   2048
#define D_MODEL 2048
#define NH      16
#define DH      128
#define BATCH   2
#define TOKENS  (BATCH * S_LEN)   // 4096

// ---------------- scratch (device globals: allocation-free) ----------------
__device__ float g_Q[TOKENS * D_MODEL];
__device__ float g_K[TOKENS * D_MODEL];
__device__ float g_V[TOKENS * D_MODEL];
__device__ float g_O[TOKENS * D_MODEL];
__device__ __half g_Ahf[TOKENS * D_MODEL];           // fp16 split A (hi)
__device__ __half g_Alf[TOKENS * D_MODEL];           // fp16 split A (lo)
__device__ __half g_Bhf[D_MODEL * D_MODEL];          // fp16 transposed W [N][K]
__device__ __nv_bfloat16 g_Qh[TOKENS * D_MODEL];
__device__ __nv_bfloat16 g_Ql[TOKENS * D_MODEL];
__device__ __nv_bfloat16 g_Kh[TOKENS * D_MODEL];
__device__ __nv_bfloat16 g_Kl[TOKENS * D_MODEL];
__device__ __nv_bfloat16 g_Vh[TOKENS * D_MODEL];
__device__ __nv_bfloat16 g_Vl[TOKENS * D_MODEL];
__device__ float2 g_cs[S_LEN * 64];

// ---------------- common asm helpers ---------------------------------------
#define MMA16816(d, a, b)                                                     \
    asm volatile(                                                             \
        "mma.sync.aligned.m16n8k16.row.col.f32.bf16.bf16.f32 "                \
        "{%0,%1,%2,%3},{%4,%5,%6,%7},{%8,%9},{%0,%1,%2,%3};\n"                \
        : "+f"(d[0]), "+f"(d[1]), "+f"(d[2]), "+f"(d[3])                      \
        : "r"(a[0]), "r"(a[1]), "r"(a[2]), "r"(a[3]), "r"(b[0]), "r"(b[1]))

#define MMA16816F(d, a, b)                                                    \
    asm volatile(                                                             \
        "mma.sync.aligned.m16n8k16.row.col.f32.f16.f16.f32 "                  \
        "{%0,%1,%2,%3},{%4,%5,%6,%7},{%8,%9},{%0,%1,%2,%3};\n"                \
        : "+f"(d[0]), "+f"(d[1]), "+f"(d[2]), "+f"(d[3])                      \
        : "r"(a[0]), "r"(a[1]), "r"(a[2]), "r"(a[3]), "r"(b[0]), "r"(b[1]))

#define LDSM_X4(d0, d1, d2, d3, addr)                                         \
    asm volatile("ldmatrix.sync.aligned.m8n8.x4.shared.b16 {%0,%1,%2,%3}, [%4];" \
                 : "=r"(d0), "=r"(d1), "=r"(d2), "=r"(d3) : "r"(addr))

#define LDSM_X4_T(d0, d1, d2, d3, addr)                                       \
    asm volatile("ldmatrix.sync.aligned.m8n8.x4.trans.shared.b16 {%0,%1,%2,%3}, [%4];" \
                 : "=r"(d0), "=r"(d1), "=r"(d2), "=r"(d3) : "r"(addr))

#define CP16(dst, src)                                                        \
    asm volatile("cp.async.cg.shared.global [%0], [%1], 16;\n"                \
                 :: "r"(dst), "l"(src))
#define CP_COMMIT() asm volatile("cp.async.commit_group;\n" ::: "memory")
#define CP_WAIT0()  asm volatile("cp.async.wait_group 0;\n" ::: "memory")

__device__ __forceinline__ void split2pack(float x, float y,
                                           uint32_t& hi, uint32_t& lo)
{
    __nv_bfloat16 hx = __float2bfloat16(x), hy = __float2bfloat16(y);
    __nv_bfloat16 lx = __float2bfloat16(x - __bfloat162float(hx));
    __nv_bfloat16 ly = __float2bfloat16(y - __bfloat162float(hy));
    __nv_bfloat162 th = __halves2bfloat162(hx, hy);
    __nv_bfloat162 tl = __halves2bfloat162(lx, ly);
    hi = *reinterpret_cast<uint32_t*>(&th);
    lo = *reinterpret_cast<uint32_t*>(&tl);
}

// ---------------- rope table (fp64 once, tiny) -----------------------------
__global__ void rope_table_kernel()
{
    int idx = blockIdx.x * blockDim.x + threadIdx.x;
    if (idx >= S_LEN * 64) return;
    int pos = idx >> 6;
    int i   = idx & 63;
    double inv = exp(-((double)(2 * i) / 128.0) * 9.210340371976184);
    double f   = (double)pos * inv;
    g_cs[idx] = make_float2((float)cos(f), (float)sin(f));
}

// ---------------- split fp32 -> fp16 hi/lo (GEMM A-side) -------------------
__global__ void split16_kernel(const float* __restrict__ x,
                               __half* __restrict__ hi,
                               __half* __restrict__ lo, int n2)
{
    int i = blockIdx.x * blockDim.x + threadIdx.x;
    if (i >= n2) return;
    float2 v = ((const float2*)x)[i];
    __half h0 = __float2half(v.x);
    __half h1 = __float2half(v.y);
    __half l0 = __float2half(v.x - __half2float(h0));
    __half l1 = __float2half(v.y - __half2float(h1));
    ((__half2*)hi)[i] = __halves2half2(h0, h1);
    ((__half2*)lo)[i] = __halves2half2(l0, l1);
}

// ---------------- split fp32 -> bf16 hi/lo (attention V) -------------------
__global__ void split_kernel(const float* __restrict__ x,
                             __nv_bfloat16* __restrict__ hi,
                             __nv_bfloat16* __restrict__ lo, int n2)
{
    int i = blockIdx.x * blockDim.x + threadIdx.x;
    if (i >= n2) return;
    float2 v = ((const float2*)x)[i];
    __nv_bfloat16 h0 = __float2bfloat16(v.x);
    __nv_bfloat16 h1 = __float2bfloat16(v.y);
    __nv_bfloat16 l0 = __float2bfloat16(v.x - __bfloat162float(h0));
    __nv_bfloat16 l1 = __float2bfloat16(v.y - __bfloat162float(h1));
    ((__nv_bfloat162*)hi)[i] = __halves2bfloat162(h0, h1);
    ((__nv_bfloat162*)lo)[i] = __halves2bfloat162(l0, l1);
}

// ---------------- rope + split: fp32 in -> bf16 hi/lo out ------------------
__global__ void rope_split_kernel(const float* __restrict__ X,
                                  __nv_bfloat16* __restrict__ Xh,
                                  __nv_bfloat16* __restrict__ Xl, float scale)
{
    int idx = blockIdx.x * blockDim.x + threadIdx.x;
    if (idx >= TOKENS * NH * 64) return;
    int i  = idx & 63;
    int hh = (idx >> 6) & (NH - 1);
    int t  = idx >> 10;
    int pos = t & (S_LEN - 1);

    float2 cs = g_cs[pos * 64 + i];
    const float* p = X + (size_t)t * D_MODEL + hh * DH;
    float x1 = p[i];
    float x2 = p[i + 64];
    float y1 = (x1 * cs.x - x2 * cs.y) * scale;
    float y2 = (x2 * cs.x + x1 * cs.y) * scale;

    size_t o = (size_t)t * D_MODEL + hh * DH;
    __nv_bfloat16 h1 = __float2bfloat16(y1);
    __nv_bfloat16 h2 = __float2bfloat16(y2);
    Xh[o + i]      = h1;
    Xl[o + i]      = __float2bfloat16(y1 - __bfloat162float(h1));
    Xh[o + i + 64] = h2;
    Xl[o + i + 64] = __float2bfloat16(y2 - __bfloat162float(h2));
}

// ---------------- transpose: W[K][N] -> WT[N][K] fp16 ----------------------
__global__ void tsplit16_kernel(const float* __restrict__ W,
                                __half* __restrict__ hiT)
{
    __shared__ float tile[32][33];
    int tx = threadIdx.x, ty = threadIdx.y;
    int x0 = blockIdx.x * 32, y0 = blockIdx.y * 32;
    #pragma unroll
    for (int j = 0; j < 32; j += 8)
        tile[ty + j][tx] = W[(size_t)(y0 + ty + j) * D_MODEL + x0 + tx];
    __syncthreads();
    #pragma unroll
    for (int j = 0; j < 32; j += 8) {
        float v = tile[tx][ty + j];
        hiT[(size_t)(x0 + ty + j) * D_MODEL + y0 + tx] = __float2half(v);
    }
}

// ---------------- fp16x2 GEMM: 2-stage cp.async, 1 barrier/tile ------------
// C = (Ah + Al) @ Bh^T : two MMA products; dropped A@Blo term ~2^-12 rel.
#define TBM 128
#define TBN 128
#define TBK 32
#define TS  40                     // halves per row (padded)
#define TSZ (TBM * TS)
#define ASZ (TSZ * 2)              // bytes per array (10240)
#define STAGE_B (3 * ASZ)          // bytes per stage (30720): Ah, Al, Bh
#define GEMM_SMEM (2 * STAGE_B)    // 61440 B -> 2 CTA/SM

__global__ void __launch_bounds__(256, 2) gemm_fp16x2_kernel(
    const __half* __restrict__ Ah, const __half* __restrict__ Al,
    const __half* __restrict__ BTh, float* __restrict__ C)
{
    const int K = D_MODEL, N = D_MODEL;
    extern __shared__ __half gsm[];
    const uint32_t cBase = (uint32_t)__cvta_generic_to_shared(gsm);

    const int t = threadIdx.x;
    const int bm = blockIdx.y, bn = blockIdx.x;
    const int warp = t >> 5, lane = t & 31;
    const int wm = warp >> 2;
    const int wn = warp & 3;
    const int g  = lane >> 2;
    const int tq = lane & 3;

    const uint32_t aoff = (uint32_t)(((wm * 64 + (lane & 15)) * TS + ((lane >> 4) * 8)) * 2);
    const uint32_t boff = (uint32_t)(((wn * 32 + (lane & 7) + ((lane >> 4) * 8)) * TS
                                     + (((lane >> 3) & 1) * 8)) * 2);
    const int lr = t >> 2;
    const int lc = (t & 3) * 8;

    float acc[4][4][4];
    #pragma unroll
    for (int a = 0; a < 4; a++)
        #pragma unroll
        for (int b = 0; b < 4; b++)
            #pragma unroll
            for (int c = 0; c < 4; c++) acc[a][b][c] = 0.0f;

    const int KT = K / TBK;   // 64

    auto load_stage = [&](int kt, int buf) {
        uint32_t sb = cBase + (uint32_t)buf * STAGE_B;
        int k0 = kt * TBK;
        #pragma unroll
        for (int rep = 0; rep < 2; rep++) {
            int r = lr + rep * 64;
            size_t ga = (size_t)(bm * TBM + r) * K + k0 + lc;
            size_t gb = (size_t)(bn * TBN + r) * K + k0 + lc;
            uint32_t ds = sb + (uint32_t)((r * TS + lc) * 2);
            CP16(ds,            Ah + ga);
            CP16(ds + ASZ,      Al + ga);
            CP16(ds + 2 * ASZ,  BTh + gb);
        }
    };

    load_stage(0, 0);
    CP_COMMIT();

    for (int kt = 0; kt < KT; kt++) {
        CP_WAIT0();
        __syncthreads();   // one barrier: stage kt visible + old-buf readers fenced
        if (kt + 1 < KT) {
            load_stage(kt + 1, (kt + 1) & 1);
            CP_COMMIT();
        }

        const uint32_t sb = cBase + (uint32_t)(kt & 1) * STAGE_B;
        #pragma unroll
        for (int ks = 0; ks < 2; ks++) {
            const uint32_t kofs = ks * 32;
            uint32_t fah[4][4], fal[4][4], fbh[4][2];
            #pragma unroll
            for (int mf = 0; mf < 4; mf++) {
                uint32_t ad = sb + aoff + mf * (16 * TS * 2) + kofs;
                LDSM_X4(fah[mf][0], fah[mf][1], fah[mf][2], fah[mf][3], ad);
                LDSM_X4(fal[mf][0], fal[mf][1], fal[mf][2], fal[mf][3], ad + ASZ);
            }
            #pragma unroll
            for (int p = 0; p < 2; p++) {
                uint32_t bd = sb + 2 * ASZ + boff + p * (16 * TS * 2) + kofs;
                LDSM_X4(fbh[2*p][0], fbh[2*p][1], fbh[2*p+1][0], fbh[2*p+1][1], bd);
            }
            #pragma unroll
            for (int mf = 0; mf < 4; mf++)
                #pragma unroll
                for (int nf = 0; nf < 4; nf++) {
                    MMA16816F(acc[mf][nf], fah[mf], fbh[nf]);
                    MMA16816F(acc[mf][nf], fal[mf], fbh[nf]);
                }
        }
    }

    #pragma unroll
    for (int mf = 0; mf < 4; mf++) {
        int row = bm * TBM + wm * 64 + mf * 16 + g;
        #pragma unroll
        for (int nf = 0; nf < 4; nf++) {
            int col = bn * TBN + wn * 32 + nf * 8 + tq * 2;
            *(float2*)&C[(size_t)row * N + col] =
                make_float2(acc[mf][nf][0], acc[mf][nf][1]);
            *(float2*)&C[(size_t)(row + 8) * N + col] =
                make_float2(acc[mf][nf][2], acc[mf][nf][3]);
        }
    }
}

// ---------------- tensor-core flash attention (bf16x3, causal, BQ=64) ------
#define AT_SD 136          // smem stride (halves): 272B, LDSM conflict-free
#define AT_TILE (64 * AT_SD)
#define ATT_SMEM (6 * AT_TILE * 2)   // 104448 B

__global__ void __launch_bounds__(128) attn_tc_kernel(
    const __nv_bfloat16* __restrict__ Qh, const __nv_bfloat16* __restrict__ Ql,
    const __nv_bfloat16* __restrict__ Kh, const __nv_bfloat16* __restrict__ Kl,
    const __nv_bfloat16* __restrict__ Vh, const __nv_bfloat16* __restrict__ Vl,
    float* __restrict__ O)
{
    const int b = blockIdx.z, h = blockIdx.y, qb = blockIdx.x;
    const int tid = threadIdx.x, warp = tid >> 5, lane = tid & 31;
    const int g = lane >> 2, tq = lane & 3;

    extern __shared__ __nv_bfloat16 sh[];
    __nv_bfloat16* sQh = sh;
    __nv_bfloat16* sQl = sQh + AT_TILE;
    __nv_bfloat16* sKh = sQl + AT_TILE;
    __nv_bfloat16* sKl = sKh + AT_TILE;
    __nv_bfloat16* sVh = sKl + AT_TILE;
    __nv_bfloat16* sVl = sVh + AT_TILE;

    const size_t base = ((size_t)b * S_LEN) * D_MODEL + (size_t)h * DH;

    for (int i = tid; i < 64 * 16; i += 128) {
        int r = i >> 4, c = (i & 15) << 3;
        size_t src = base + (size_t)(qb * 64 + r) * D_MODEL + c;
        *(uint4*)&sQh[r * AT_SD + c] = *(const uint4*)(Qh + src);
        *(uint4*)&sQl[r * AT_SD + c] = *(const uint4*)(Ql + src);
    }

    float o[16][4];
    #pragma unroll
    for (int nf = 0; nf < 16; nf++)
        #pragma unroll
        for (int c = 0; c < 4; c++) o[nf][c] = 0.0f;
    float mr0 = -INFINITY, mr1 = -INFINITY, lr0 = 0.0f, lr1 = 0.0f;

    const uint32_t cQh = (uint32_t)__cvta_generic_to_shared(sQh);
    const uint32_t cQl = (uint32_t)__cvta_generic_to_shared(sQl);
    const uint32_t cKh = (uint32_t)__cvta_generic_to_shared(sKh);
    const uint32_t cKl = (uint32_t)__cvta_generic_to_shared(sKl);
    const uint32_t cVh = (uint32_t)__cvta_generic_to_shared(sVh);
    const uint32_t cVl = (uint32_t)__cvta_generic_to_shared(sVl);
    const uint32_t aoff  = (uint32_t)(((warp * 16 + (lane & 15)) * AT_SD + ((lane >> 4) * 8)) * 2);
    const uint32_t boffK = (uint32_t)((((lane & 7) + ((lane >> 4) * 8)) * AT_SD
                                      + (((lane >> 3) & 1) * 8)) * 2);
    const uint32_t boffVt = (uint32_t)(((lane & 15) * AT_SD + ((lane >> 4) * 8)) * 2);

    for (int kb = 0; kb <= qb; kb++) {
        __syncthreads();
        for (int i = tid; i < 64 * 16; i += 128) {
            int r = i >> 4, c = (i & 15) << 3;
            size_t src = base + (size_t)(kb * 64 + r) * D_MODEL + c;
            *(uint4*)&sKh[r * AT_SD + c] = *(const uint4*)(Kh + src);
            *(uint4*)&sKl[r * AT_SD + c] = *(const uint4*)(Kl + src);
            *(uint4*)&sVh[r * AT_SD + c] = *(const uint4*)(Vh + src);
            *(uint4*)&sVl[r * AT_SD + c] = *(const uint4*)(Vl + src);
        }
        __syncthreads();

        float s[8][4];
        #pragma unroll
        for (int tt = 0; tt < 8; tt++)
            #pragma unroll
            for (int c = 0; c < 4; c++) s[tt][c] = 0.0f;

        #pragma unroll
        for (int ks = 0; ks < 8; ks++) {
            uint32_t qh[4], ql[4];
            LDSM_X4(qh[0], qh[1], qh[2], qh[3], cQh + aoff + ks * 32);
            LDSM_X4(ql[0], ql[1], ql[2], ql[3], cQl + aoff + ks * 32);
            #pragma unroll
            for (int p = 0; p < 4; p++) {
                uint32_t kh[4], kl[4];
                uint32_t bd = boffK + p * (16 * AT_SD * 2) + ks * 32;
                LDSM_X4(kh[0], kh[1], kh[2], kh[3], cKh + bd);
                LDSM_X4(kl[0], kl[1], kl[2], kl[3], cKl + bd);
                uint32_t bh0[2] = {kh[0], kh[1]}, bh1[2] = {kh[2], kh[3]};
                uint32_t bl0[2] = {kl[0], kl[1]}, bl1[2] = {kl[2], kl[3]};
                MMA16816(s[2*p],     qh, bh0);
                MMA16816(s[2*p],     ql, bh0);
                MMA16816(s[2*p],     qh, bl0);
                MMA16816(s[2*p + 1], qh, bh1);
                MMA16816(s[2*p + 1], ql, bh1);
                MMA16816(s[2*p + 1], qh, bl1);
            }
        }

        if (kb == qb) {
            int r0 = warp * 16 + g, r1 = r0 + 8;
            #pragma unroll
            for (int tt = 0; tt < 8; tt++) {
                int c0 = tt * 8 + tq * 2;
                if (c0     > r0) s[tt][0] = -INFINITY;
                if (c0 + 1 > r0) s[tt][1] = -INFINITY;
                if (c0     > r1) s[tt][2] = -INFINITY;
                if (c0 + 1 > r1) s[tt][3] = -INFINITY;
            }
        }

        float mx0 = -INFINITY, mx1 = -INFINITY;
        #pragma unroll
        for (int tt = 0; tt < 8; tt++) {
            mx0 = fmaxf(mx0, fmaxf(s[tt][0], s[tt][1]));
            mx1 = fmaxf(mx1, fmaxf(s[tt][2], s[tt][3]));
        }
        mx0 = fmaxf(mx0, __shfl_xor_sync(0xffffffffu, mx0, 1));
        mx0 = fmaxf(mx0, __shfl_xor_sync(0xffffffffu, mx0, 2));
        mx1 = fmaxf(mx1, __shfl_xor_sync(0xffffffffu, mx1, 1));
        mx1 = fmaxf(mx1, __shfl_xor_sync(0xffffffffu, mx1, 2));

        float mn0 = fmaxf(mr0, mx0), mn1 = fmaxf(mr1, mx1);
        float al0 = __expf(mr0 - mn0), al1 = __expf(mr1 - mn1);
        float sum0 = 0.0f, sum1 = 0.0f;
        #pragma unroll
        for (int tt = 0; tt < 8; tt++) {
            s[tt][0] = __expf(s[tt][0] - mn0);
            s[tt][1] = __expf(s[tt][1] - mn0);
            s[tt][2] = __expf(s[tt][2] - mn1);
            s[tt][3] = __expf(s[tt][3] - mn1);
            sum0 += s[tt][0] + s[tt][1];
            sum1 += s[tt][2] + s[tt][3];
        }
        sum0 += __shfl_xor_sync(0xffffffffu, sum0, 1);
        sum0 += __shfl_xor_sync(0xffffffffu, sum0, 2);
        sum1 += __shfl_xor_sync(0xffffffffu, sum1, 1);
        sum1 += __shfl_xor_sync(0xffffffffu, sum1, 2);
        lr0 = lr0 * al0 + sum0;
        lr1 = lr1 * al1 + sum1;
        mr0 = mn0;
        mr1 = mn1;
        #pragma unroll
        for (int nf = 0; nf < 16; nf++) {
            o[nf][0] *= al0; o[nf][1] *= al0;
            o[nf][2] *= al1; o[nf][3] *= al1;
        }

        #pragma unroll
        for (int j = 0; j < 4; j++) {
            uint32_t ph[4], pl[4];
            split2pack(s[2*j][0],     s[2*j][1],     ph[0], pl[0]);
            split2pack(s[2*j][2],     s[2*j][3],     ph[1], pl[1]);
            split2pack(s[2*j + 1][0], s[2*j + 1][1], ph[2], pl[2]);
            split2pack(s[2*j + 1][2], s[2*j + 1][3], ph[3], pl[3]);
            #pragma unroll
            for (int dtile = 0; dtile < 8; dtile++) {
                uint32_t vh4[4], vl4[4];
                uint32_t bd = boffVt + (uint32_t)((j * 16 * AT_SD + dtile * 16) * 2);
                LDSM_X4_T(vh4[0], vh4[1], vh4[2], vh4[3], cVh + bd);
                LDSM_X4_T(vl4[0], vl4[1], vl4[2], vl4[3], cVl + bd);
                uint32_t bh0[2] = {vh4[0], vh4[1]}, bh1[2] = {vh4[2], vh4[3]};
                uint32_t bl0[2] = {vl4[0], vl4[1]}, bl1[2] = {vl4[2], vl4[3]};
                MMA16816(o[2*dtile],     ph, bh0);
                MMA16816(o[2*dtile],     pl, bh0);
                MMA16816(o[2*dtile],     ph, bl0);
                MMA16816(o[2*dtile + 1], ph, bh1);
                MMA16816(o[2*dtile + 1], pl, bh1);
                MMA16816(o[2*dtile + 1], ph, bl1);
            }
        }
    }

    float inv0 = 1.0f / lr0, inv1 = 1.0f / lr1;
    int r0 = qb * 64 + warp * 16 + g;
    #pragma unroll
    for (int dtile = 0; dtile < 8; dtile++) {
        #pragma unroll
        for (int u = 0; u < 2; u++) {
            int nf = 2 * dtile + u;
            int c = dtile * 16 + u * 8 + tq * 2;
            *(float2*)&O[base + (size_t)r0 * D_MODEL + c] =
                make_float2(o[nf][0] * inv0, o[nf][1] * inv0);
            *(float2*)&O[base + (size_t)(r0 + 8) * D_MODEL + c] =
                make_float2(o[nf][2] * inv1, o[nf][3] * inv1);
        }
    }
}

// ---------------- launch ----------------------------------------------------
extern "C" void kernel_launch(void* const* d_in, const int* in_sizes, int n_in,
                              void* d_out, int out_size)
{
    (void)in_sizes; (void)n_in; (void)out_size;
    const float* hidden = (const float*)d_in[0];
    const float* Wq = (const float*)d_in[3];
    const float* Wk = (const float*)d_in[4];
    const float* Wv = (const float*)d_in[5];
    const float* Wo = (const float*)d_in[6];
    float* out = (float*)d_out;

    float *Qp, *Kp, *Vp, *Op;
    __half *Ahp, *Alp, *Bhp;
    __nv_bfloat16 *Qhp, *Qlp, *Khp, *Klp, *Vhp, *Vlp;
    cudaGetSymbolAddress((void**)&Qp, g_Q);
    cudaGetSymbolAddress((void**)&Kp, g_K);
    cudaGetSymbolAddress((void**)&Vp, g_V);
    cudaGetSymbolAddress((void**)&Op, g_O);
    cudaGetSymbolAddress((void**)&Ahp, g_Ahf);
    cudaGetSymbolAddress((void**)&Alp, g_Alf);
    cudaGetSymbolAddress((void**)&Bhp, g_Bhf);
    cudaGetSymbolAddress((void**)&Qhp, g_Qh);
    cudaGetSymbolAddress((void**)&Qlp, g_Ql);
    cudaGetSymbolAddress((void**)&Khp, g_Kh);
    cudaGetSymbolAddress((void**)&Klp, g_Kl);
    cudaGetSymbolAddress((void**)&Vhp, g_Vh);
    cudaGetSymbolAddress((void**)&Vlp, g_Vl);

    rope_table_kernel<<<(S_LEN * 64 + 255) / 256, 256>>>();

    int n2 = TOKENS * D_MODEL / 2;
    split16_kernel<<<(n2 + 255) / 256, 256>>>(hidden, Ahp, Alp, n2);

    dim3 tgrid(D_MODEL / 32, D_MODEL / 32);
    dim3 tblk(32, 8);
    dim3 ggrid(D_MODEL / TBN, TOKENS / TBM);

    cudaFuncSetAttribute(gemm_fp16x2_kernel,
                         cudaFuncAttributeMaxDynamicSharedMemorySize, GEMM_SMEM);

    tsplit16_kernel<<<tgrid, tblk>>>(Wq, Bhp);
    gemm_fp16x2_kernel<<<ggrid, 256, GEMM_SMEM>>>(Ahp, Alp, Bhp, Qp);
    tsplit16_kernel<<<tgrid, tblk>>>(Wk, Bhp);
    gemm_fp16x2_kernel<<<ggrid, 256, GEMM_SMEM>>>(Ahp, Alp, Bhp, Kp);
    tsplit16_kernel<<<tgrid, tblk>>>(Wv, Bhp);
    gemm_fp16x2_kernel<<<ggrid, 256, GEMM_SMEM>>>(Ahp, Alp, Bhp, Vp);

    int nrope = TOKENS * NH * 64;
    rope_split_kernel<<<(nrope + 255) / 256, 256>>>(Qp, Qhp, Qlp, 0.08838834764831845f);
    rope_split_kernel<<<(nrope + 255) / 256, 256>>>(Kp, Khp, Klp, 1.0f);
    split_kernel<<<(n2 + 255) / 256, 256>>>(Vp, Vhp, Vlp, n2);

    cudaFuncSetAttribute(attn_tc_kernel,
                         cudaFuncAttributeMaxDynamicSharedMemorySize, ATT_SMEM);
    attn_tc_kernel<<<dim3(S_LEN / 64, NH, BATCH), 128, ATT_SMEM>>>(
        Qhp, Qlp, Khp, Klp, Vhp, Vlp, Op);

    split16_kernel<<<(n2 + 255) / 256, 256>>>(Op, Ahp, Alp, n2);
    tsplit16_kernel<<<tgrid, tblk>>>(Wo, Bhp);
    gemm_fp16x2_kernel<<<ggrid, 256, GEMM_SMEM>>>(Ahp, Alp, Bhp, out);
}

// round 16
// speedup vs baseline: 1.6370x; 1.1843x over previous
#include <cuda_runtime.h>
#include <cuda_fp16.h>
#include <cstdint>
#include <math.h>

#define S_LEN   2048
#define D_MODEL 2048
#define NH      16
#define DH      128
#define BATCH   2
#define TOKENS  (BATCH * S_LEN)   // 4096

// ---------------- scratch (device globals: allocation-free) ----------------
__device__ float g_Q[TOKENS * D_MODEL];
__device__ float g_K[TOKENS * D_MODEL];
__device__ float g_V[TOKENS * D_MODEL];
__device__ float g_O[TOKENS * D_MODEL];
__device__ __half g_Ahf[TOKENS * D_MODEL];           // fp16 split A (hi)
__device__ __half g_Alf[TOKENS * D_MODEL];           // fp16 split A (lo)
__device__ __half g_Bhf[D_MODEL * D_MODEL];          // fp16 transposed W [N][K]
__device__ __half g_Qh16[TOKENS * D_MODEL];
__device__ __half g_Ql16[TOKENS * D_MODEL];
__device__ __half g_Kh16[TOKENS * D_MODEL];
__device__ __half g_Vh16[TOKENS * D_MODEL];
__device__ float2 g_cs[S_LEN * 64];

// ---------------- common asm helpers ---------------------------------------
#define MMA16816F(d, a, b)                                                    \
    asm volatile(                                                             \
        "mma.sync.aligned.m16n8k16.row.col.f32.f16.f16.f32 "                  \
        "{%0,%1,%2,%3},{%4,%5,%6,%7},{%8,%9},{%0,%1,%2,%3};\n"                \
        : "+f"(d[0]), "+f"(d[1]), "+f"(d[2]), "+f"(d[3])                      \
        : "r"(a[0]), "r"(a[1]), "r"(a[2]), "r"(a[3]), "r"(b[0]), "r"(b[1]))

#define LDSM_X4(d0, d1, d2, d3, addr)                                         \
    asm volatile("ldmatrix.sync.aligned.m8n8.x4.shared.b16 {%0,%1,%2,%3}, [%4];" \
                 : "=r"(d0), "=r"(d1), "=r"(d2), "=r"(d3) : "r"(addr))

#define LDSM_X4_T(d0, d1, d2, d3, addr)                                       \
    asm volatile("ldmatrix.sync.aligned.m8n8.x4.trans.shared.b16 {%0,%1,%2,%3}, [%4];" \
                 : "=r"(d0), "=r"(d1), "=r"(d2), "=r"(d3) : "r"(addr))

#define CP16(dst, src)                                                        \
    asm volatile("cp.async.cg.shared.global [%0], [%1], 16;\n"                \
                 :: "r"(dst), "l"(src))
#define CP_COMMIT() asm volatile("cp.async.commit_group;\n" ::: "memory")
#define CP_WAIT0()  asm volatile("cp.async.wait_group 0;\n" ::: "memory")

__device__ __forceinline__ void split2pack16(float x, float y,
                                             uint32_t& hi, uint32_t& lo)
{
    __half hx = __float2half(x), hy = __float2half(y);
    __half lx = __float2half(x - __half2float(hx));
    __half ly = __float2half(y - __half2float(hy));
    __half2 th = __halves2half2(hx, hy);
    __half2 tl = __halves2half2(lx, ly);
    hi = *reinterpret_cast<uint32_t*>(&th);
    lo = *reinterpret_cast<uint32_t*>(&tl);
}

// ---------------- rope table (fp64 once, tiny) -----------------------------
__global__ void rope_table_kernel()
{
    int idx = blockIdx.x * blockDim.x + threadIdx.x;
    if (idx >= S_LEN * 64) return;
    int pos = idx >> 6;
    int i   = idx & 63;
    double inv = exp(-((double)(2 * i) / 128.0) * 9.210340371976184);
    double f   = (double)pos * inv;
    g_cs[idx] = make_float2((float)cos(f), (float)sin(f));
}

// ---------------- split fp32 -> fp16 hi/lo ---------------------------------
__global__ void split16_kernel(const float* __restrict__ x,
                               __half* __restrict__ hi,
                               __half* __restrict__ lo, int n2)
{
    int i = blockIdx.x * blockDim.x + threadIdx.x;
    if (i >= n2) return;
    float2 v = ((const float2*)x)[i];
    __half h0 = __float2half(v.x);
    __half h1 = __float2half(v.y);
    __half l0 = __float2half(v.x - __half2float(h0));
    __half l1 = __float2half(v.y - __half2float(h1));
    ((__half2*)hi)[i] = __halves2half2(h0, h1);
    ((__half2*)lo)[i] = __halves2half2(l0, l1);
}

// ---------------- fp32 -> fp16 (hi only; for V) ----------------------------
__global__ void half_kernel(const float* __restrict__ x,
                            __half* __restrict__ hi, int n2)
{
    int i = blockIdx.x * blockDim.x + threadIdx.x;
    if (i >= n2) return;
    float2 v = ((const float2*)x)[i];
    ((__half2*)hi)[i] = __halves2half2(__float2half(v.x), __float2half(v.y));
}

// ---------------- rope + split fp16 hi/lo (for Q; no scale) ----------------
__global__ void rope_split16_kernel(const float* __restrict__ X,
                                    __half* __restrict__ Xh,
                                    __half* __restrict__ Xl)
{
    int idx = blockIdx.x * blockDim.x + threadIdx.x;
    if (idx >= TOKENS * NH * 64) return;
    int i  = idx & 63;
    int hh = (idx >> 6) & (NH - 1);
    int t  = idx >> 10;
    int pos = t & (S_LEN - 1);

    float2 cs = g_cs[pos * 64 + i];
    const float* p = X + (size_t)t * D_MODEL + hh * DH;
    float x1 = p[i];
    float x2 = p[i + 64];
    float y1 = x1 * cs.x - x2 * cs.y;
    float y2 = x2 * cs.x + x1 * cs.y;

    size_t o = (size_t)t * D_MODEL + hh * DH;
    __half h1 = __float2half(y1);
    __half h2 = __float2half(y2);
    Xh[o + i]      = h1;
    Xl[o + i]      = __float2half(y1 - __half2float(h1));
    Xh[o + i + 64] = h2;
    Xl[o + i + 64] = __float2half(y2 - __half2float(h2));
}

// ---------------- rope + fp16 hi only (for K) ------------------------------
__global__ void rope_half_kernel(const float* __restrict__ X,
                                 __half* __restrict__ Xh)
{
    int idx = blockIdx.x * blockDim.x + threadIdx.x;
    if (idx >= TOKENS * NH * 64) return;
    int i  = idx & 63;
    int hh = (idx >> 6) & (NH - 1);
    int t  = idx >> 10;
    int pos = t & (S_LEN - 1);

    float2 cs = g_cs[pos * 64 + i];
    const float* p = X + (size_t)t * D_MODEL + hh * DH;
    float x1 = p[i];
    float x2 = p[i + 64];
    size_t o = (size_t)t * D_MODEL + hh * DH;
    Xh[o + i]      = __float2half(x1 * cs.x - x2 * cs.y);
    Xh[o + i + 64] = __float2half(x2 * cs.x + x1 * cs.y);
}

// ---------------- transpose: W[K][N] -> WT[N][K] fp16 ----------------------
__global__ void tsplit16_kernel(const float* __restrict__ W,
                                __half* __restrict__ hiT)
{
    __shared__ float tile[32][33];
    int tx = threadIdx.x, ty = threadIdx.y;
    int x0 = blockIdx.x * 32, y0 = blockIdx.y * 32;
    #pragma unroll
    for (int j = 0; j < 32; j += 8)
        tile[ty + j][tx] = W[(size_t)(y0 + ty + j) * D_MODEL + x0 + tx];
    __syncthreads();
    #pragma unroll
    for (int j = 0; j < 32; j += 8) {
        float v = tile[tx][ty + j];
        hiT[(size_t)(x0 + ty + j) * D_MODEL + y0 + tx] = __float2half(v);
    }
}

// ---------------- fp16x2 GEMM: 2-stage cp.async, 1 barrier/tile ------------
#define TBM 128
#define TBN 128
#define TBK 32
#define TS  40                     // halves per row (padded)
#define TSZ (TBM * TS)
#define ASZ (TSZ * 2)              // bytes per array (10240)
#define STAGE_B (3 * ASZ)          // bytes per stage (30720): Ah, Al, Bh
#define GEMM_SMEM (2 * STAGE_B)    // 61440 B -> 2 CTA/SM

__global__ void __launch_bounds__(256, 2) gemm_fp16x2_kernel(
    const __half* __restrict__ Ah, const __half* __restrict__ Al,
    const __half* __restrict__ BTh, float* __restrict__ C)
{
    const int K = D_MODEL, N = D_MODEL;
    extern __shared__ __half gsm[];
    const uint32_t cBase = (uint32_t)__cvta_generic_to_shared(gsm);

    const int t = threadIdx.x;
    const int bm = blockIdx.y, bn = blockIdx.x;
    const int warp = t >> 5, lane = t & 31;
    const int wm = warp >> 2;
    const int wn = warp & 3;
    const int g  = lane >> 2;
    const int tq = lane & 3;

    const uint32_t aoff = (uint32_t)(((wm * 64 + (lane & 15)) * TS + ((lane >> 4) * 8)) * 2);
    const uint32_t boff = (uint32_t)(((wn * 32 + (lane & 7) + ((lane >> 4) * 8)) * TS
                                     + (((lane >> 3) & 1) * 8)) * 2);
    const int lr = t >> 2;
    const int lc = (t & 3) * 8;

    float acc[4][4][4];
    #pragma unroll
    for (int a = 0; a < 4; a++)
        #pragma unroll
        for (int b = 0; b < 4; b++)
            #pragma unroll
            for (int c = 0; c < 4; c++) acc[a][b][c] = 0.0f;

    const int KT = K / TBK;   // 64

    auto load_stage = [&](int kt, int buf) {
        uint32_t sb = cBase + (uint32_t)buf * STAGE_B;
        int k0 = kt * TBK;
        #pragma unroll
        for (int rep = 0; rep < 2; rep++) {
            int r = lr + rep * 64;
            size_t ga = (size_t)(bm * TBM + r) * K + k0 + lc;
            size_t gb = (size_t)(bn * TBN + r) * K + k0 + lc;
            uint32_t ds = sb + (uint32_t)((r * TS + lc) * 2);
            CP16(ds,            Ah + ga);
            CP16(ds + ASZ,      Al + ga);
            CP16(ds + 2 * ASZ,  BTh + gb);
        }
    };

    load_stage(0, 0);
    CP_COMMIT();

    for (int kt = 0; kt < KT; kt++) {
        CP_WAIT0();
        __syncthreads();   // one barrier: stage kt visible + old-buf readers fenced
        if (kt + 1 < KT) {
            load_stage(kt + 1, (kt + 1) & 1);
            CP_COMMIT();
        }

        const uint32_t sb = cBase + (uint32_t)(kt & 1) * STAGE_B;
        #pragma unroll
        for (int ks = 0; ks < 2; ks++) {
            const uint32_t kofs = ks * 32;
            uint32_t fah[4][4], fal[4][4], fbh[4][2];
            #pragma unroll
            for (int mf = 0; mf < 4; mf++) {
                uint32_t ad = sb + aoff + mf * (16 * TS * 2) + kofs;
                LDSM_X4(fah[mf][0], fah[mf][1], fah[mf][2], fah[mf][3], ad);
                LDSM_X4(fal[mf][0], fal[mf][1], fal[mf][2], fal[mf][3], ad + ASZ);
            }
            #pragma unroll
            for (int p = 0; p < 2; p++) {
                uint32_t bd = sb + 2 * ASZ + boff + p * (16 * TS * 2) + kofs;
                LDSM_X4(fbh[2*p][0], fbh[2*p][1], fbh[2*p+1][0], fbh[2*p+1][1], bd);
            }
            #pragma unroll
            for (int mf = 0; mf < 4; mf++)
                #pragma unroll
                for (int nf = 0; nf < 4; nf++) {
                    MMA16816F(acc[mf][nf], fah[mf], fbh[nf]);
                    MMA16816F(acc[mf][nf], fal[mf], fbh[nf]);
                }
        }
    }

    #pragma unroll
    for (int mf = 0; mf < 4; mf++) {
        int row = bm * TBM + wm * 64 + mf * 16 + g;
        #pragma unroll
        for (int nf = 0; nf < 4; nf++) {
            int col = bn * TBN + wn * 32 + nf * 8 + tq * 2;
            *(float2*)&C[(size_t)row * N + col] =
                make_float2(acc[mf][nf][0], acc[mf][nf][1]);
            *(float2*)&C[(size_t)(row + 8) * N + col] =
                make_float2(acc[mf][nf][2], acc[mf][nf][3]);
        }
    }
}

// ---------------- tensor-core flash attention (fp16x2, causal, BQ=64) ------
#define AT_SD 136          // smem stride (halves): 272B, LDSM conflict-free
#define AT_TILE (64 * AT_SD)
#define ATT_SMEM (4 * AT_TILE * 2)   // Qh,Ql,Kh,Vh = 69632 B -> 2-3 CTA/SM
#define SM_SCALE 0.08838834764831845f

__global__ void __launch_bounds__(128) attn_tc_kernel(
    const __half* __restrict__ Qh, const __half* __restrict__ Ql,
    const __half* __restrict__ Kh, const __half* __restrict__ Vh,
    float* __restrict__ O)
{
    const int b = blockIdx.z, h = blockIdx.y, qb = blockIdx.x;
    const int tid = threadIdx.x, warp = tid >> 5, lane = tid & 31;
    const int g = lane >> 2, tq = lane & 3;

    extern __shared__ __half sh[];
    __half* sQh = sh;
    __half* sQl = sQh + AT_TILE;
    __half* sKh = sQl + AT_TILE;
    __half* sVh = sKh + AT_TILE;

    const size_t base = ((size_t)b * S_LEN) * D_MODEL + (size_t)h * DH;

    for (int i = tid; i < 64 * 16; i += 128) {
        int r = i >> 4, c = (i & 15) << 3;
        size_t src = base + (size_t)(qb * 64 + r) * D_MODEL + c;
        *(uint4*)&sQh[r * AT_SD + c] = *(const uint4*)(Qh + src);
        *(uint4*)&sQl[r * AT_SD + c] = *(const uint4*)(Ql + src);
    }

    float o[16][4];
    #pragma unroll
    for (int nf = 0; nf < 16; nf++)
        #pragma unroll
        for (int c = 0; c < 4; c++) o[nf][c] = 0.0f;
    float mr0 = -INFINITY, mr1 = -INFINITY, lr0 = 0.0f, lr1 = 0.0f;

    const uint32_t cQh = (uint32_t)__cvta_generic_to_shared(sQh);
    const uint32_t cQl = (uint32_t)__cvta_generic_to_shared(sQl);
    const uint32_t cKh = (uint32_t)__cvta_generic_to_shared(sKh);
    const uint32_t cVh = (uint32_t)__cvta_generic_to_shared(sVh);
    const uint32_t aoff  = (uint32_t)(((warp * 16 + (lane & 15)) * AT_SD + ((lane >> 4) * 8)) * 2);
    const uint32_t boffK = (uint32_t)((((lane & 7) + ((lane >> 4) * 8)) * AT_SD
                                      + (((lane >> 3) & 1) * 8)) * 2);
    const uint32_t boffVt = (uint32_t)(((lane & 15) * AT_SD + ((lane >> 4) * 8)) * 2);

    for (int kb = 0; kb <= qb; kb++) {
        __syncthreads();
        for (int i = tid; i < 64 * 16; i += 128) {
            int r = i >> 4, c = (i & 15) << 3;
            size_t src = base + (size_t)(kb * 64 + r) * D_MODEL + c;
            *(uint4*)&sKh[r * AT_SD + c] = *(const uint4*)(Kh + src);
            *(uint4*)&sVh[r * AT_SD + c] = *(const uint4*)(Vh + src);
        }
        __syncthreads();

        float s[8][4];
        #pragma unroll
        for (int tt = 0; tt < 8; tt++)
            #pragma unroll
            for (int c = 0; c < 4; c++) s[tt][c] = 0.0f;

        #pragma unroll
        for (int ks = 0; ks < 8; ks++) {
            uint32_t qh[4], ql[4];
            LDSM_X4(qh[0], qh[1], qh[2], qh[3], cQh + aoff + ks * 32);
            LDSM_X4(ql[0], ql[1], ql[2], ql[3], cQl + aoff + ks * 32);
            #pragma unroll
            for (int p = 0; p < 4; p++) {
                uint32_t kh[4];
                uint32_t bd = boffK + p * (16 * AT_SD * 2) + ks * 32;
                LDSM_X4(kh[0], kh[1], kh[2], kh[3], cKh + bd);
                uint32_t bh0[2] = {kh[0], kh[1]}, bh1[2] = {kh[2], kh[3]};
                MMA16816F(s[2*p],     qh, bh0);
                MMA16816F(s[2*p],     ql, bh0);
                MMA16816F(s[2*p + 1], qh, bh1);
                MMA16816F(s[2*p + 1], ql, bh1);
            }
        }

        // softmax scaling (Q was NOT pre-scaled; keeps Q-lo in fp16 normal range)
        #pragma unroll
        for (int tt = 0; tt < 8; tt++)
            #pragma unroll
            for (int c = 0; c < 4; c++) s[tt][c] *= SM_SCALE;

        if (kb == qb) {
            int r0 = warp * 16 + g, r1 = r0 + 8;
            #pragma unroll
            for (int tt = 0; tt < 8; tt++) {
                int c0 = tt * 8 + tq * 2;
                if (c0     > r0) s[tt][0] = -INFINITY;
                if (c0 + 1 > r0) s[tt][1] = -INFINITY;
                if (c0     > r1) s[tt][2] = -INFINITY;
                if (c0 + 1 > r1) s[tt][3] = -INFINITY;
            }
        }

        float mx0 = -INFINITY, mx1 = -INFINITY;
        #pragma unroll
        for (int tt = 0; tt < 8; tt++) {
            mx0 = fmaxf(mx0, fmaxf(s[tt][0], s[tt][1]));
            mx1 = fmaxf(mx1, fmaxf(s[tt][2], s[tt][3]));
        }
        mx0 = fmaxf(mx0, __shfl_xor_sync(0xffffffffu, mx0, 1));
        mx0 = fmaxf(mx0, __shfl_xor_sync(0xffffffffu, mx0, 2));
        mx1 = fmaxf(mx1, __shfl_xor_sync(0xffffffffu, mx1, 1));
        mx1 = fmaxf(mx1, __shfl_xor_sync(0xffffffffu, mx1, 2));

        float mn0 = fmaxf(mr0, mx0), mn1 = fmaxf(mr1, mx1);
        float al0 = __expf(mr0 - mn0), al1 = __expf(mr1 - mn1);
        float sum0 = 0.0f, sum1 = 0.0f;
        #pragma unroll
        for (int tt = 0; tt < 8; tt++) {
            s[tt][0] = __expf(s[tt][0] - mn0);
            s[tt][1] = __expf(s[tt][1] - mn0);
            s[tt][2] = __expf(s[tt][2] - mn1);
            s[tt][3] = __expf(s[tt][3] - mn1);
            sum0 += s[tt][0] + s[tt][1];
            sum1 += s[tt][2] + s[tt][3];
        }
        sum0 += __shfl_xor_sync(0xffffffffu, sum0, 1);
        sum0 += __shfl_xor_sync(0xffffffffu, sum0, 2);
        sum1 += __shfl_xor_sync(0xffffffffu, sum1, 1);
        sum1 += __shfl_xor_sync(0xffffffffu, sum1, 2);
        lr0 = lr0 * al0 + sum0;
        lr1 = lr1 * al1 + sum1;
        mr0 = mn0;
        mr1 = mn1;
        #pragma unroll
        for (int nf = 0; nf < 16; nf++) {
            o[nf][0] *= al0; o[nf][1] *= al0;
            o[nf][2] *= al1; o[nf][3] *= al1;
        }

        #pragma unroll
        for (int j = 0; j < 4; j++) {
            uint32_t ph[4], pl[4];
            split2pack16(s[2*j][0],     s[2*j][1],     ph[0], pl[0]);
            split2pack16(s[2*j][2],     s[2*j][3],     ph[1], pl[1]);
            split2pack16(s[2*j + 1][0], s[2*j + 1][1], ph[2], pl[2]);
            split2pack16(s[2*j + 1][2], s[2*j + 1][3], ph[3], pl[3]);
            #pragma unroll
            for (int dtile = 0; dtile < 8; dtile++) {
                uint32_t vh4[4];
                uint32_t bd = boffVt + (uint32_t)((j * 16 * AT_SD + dtile * 16) * 2);
                LDSM_X4_T(vh4[0], vh4[1], vh4[2], vh4[3], cVh + bd);
                uint32_t bh0[2] = {vh4[0], vh4[1]}, bh1[2] = {vh4[2], vh4[3]};
                MMA16816F(o[2*dtile],     ph, bh0);
                MMA16816F(o[2*dtile],     pl, bh0);
                MMA16816F(o[2*dtile + 1], ph, bh1);
                MMA16816F(o[2*dtile + 1], pl, bh1);
            }
        }
    }

    float inv0 = 1.0f / lr0, inv1 = 1.0f / lr1;
    int r0 = qb * 64 + warp * 16 + g;
    #pragma unroll
    for (int dtile = 0; dtile < 8; dtile++) {
        #pragma unroll
        for (int u = 0; u < 2; u++) {
            int nf = 2 * dtile + u;
            int c = dtile * 16 + u * 8 + tq * 2;
            *(float2*)&O[base + (size_t)r0 * D_MODEL + c] =
                make_float2(o[nf][0] * inv0, o[nf][1] * inv0);
            *(float2*)&O[base + (size_t)(r0 + 8) * D_MODEL + c] =
                make_float2(o[nf][2] * inv1, o[nf][3] * inv1);
        }
    }
}

// ---------------- launch ----------------------------------------------------
extern "C" void kernel_launch(void* const* d_in, const int* in_sizes, int n_in,
                              void* d_out, int out_size)
{
    (void)in_sizes; (void)n_in; (void)out_size;
    const float* hidden = (const float*)d_in[0];
    const float* Wq = (const float*)d_in[3];
    const float* Wk = (const float*)d_in[4];
    const float* Wv = (const float*)d_in[5];
    const float* Wo = (const float*)d_in[6];
    float* out = (float*)d_out;

    float *Qp, *Kp, *Vp, *Op;
    __half *Ahp, *Alp, *Bhp;
    __half *Qhp, *Qlp, *Khp, *Vhp;
    cudaGetSymbolAddress((void**)&Qp, g_Q);
    cudaGetSymbolAddress((void**)&Kp, g_K);
    cudaGetSymbolAddress((void**)&Vp, g_V);
    cudaGetSymbolAddress((void**)&Op, g_O);
    cudaGetSymbolAddress((void**)&Ahp, g_Ahf);
    cudaGetSymbolAddress((void**)&Alp, g_Alf);
    cudaGetSymbolAddress((void**)&Bhp, g_Bhf);
    cudaGetSymbolAddress((void**)&Qhp, g_Qh16);
    cudaGetSymbolAddress((void**)&Qlp, g_Ql16);
    cudaGetSymbolAddress((void**)&Khp, g_Kh16);
    cudaGetSymbolAddress((void**)&Vhp, g_Vh16);

    rope_table_kernel<<<(S_LEN * 64 + 255) / 256, 256>>>();

    int n2 = TOKENS * D_MODEL / 2;
    split16_kernel<<<(n2 + 255) / 256, 256>>>(hidden, Ahp, Alp, n2);

    dim3 tgrid(D_MODEL / 32, D_MODEL / 32);
    dim3 tblk(32, 8);
    dim3 ggrid(D_MODEL / TBN, TOKENS / TBM);

    cudaFuncSetAttribute(gemm_fp16x2_kernel,
                         cudaFuncAttributeMaxDynamicSharedMemorySize, GEMM_SMEM);

    tsplit16_kernel<<<tgrid, tblk>>>(Wq, Bhp);
    gemm_fp16x2_kernel<<<ggrid, 256, GEMM_SMEM>>>(Ahp, Alp, Bhp, Qp);
    tsplit16_kernel<<<tgrid, tblk>>>(Wk, Bhp);
    gemm_fp16x2_kernel<<<ggrid, 256, GEMM_SMEM>>>(Ahp, Alp, Bhp, Kp);
    tsplit16_kernel<<<tgrid, tblk>>>(Wv, Bhp);
    gemm_fp16x2_kernel<<<ggrid, 256, GEMM_SMEM>>>(Ahp, Alp, Bhp, Vp);

    int nrope = TOKENS * NH * 64;
    rope_split16_kernel<<<(nrope + 255) / 256, 256>>>(Qp, Qhp, Qlp);
    rope_half_kernel<<<(nrope + 255) / 256, 256>>>(Kp, Khp);
    half_kernel<<<(n2 + 255) / 256, 256>>>(Vp, Vhp, n2);

    cudaFuncSetAttribute(attn_tc_kernel,
                         cudaFuncAttributeMaxDynamicSharedMemorySize, ATT_SMEM);
    attn_tc_kernel<<<dim3(S_LEN / 64, NH, BATCH), 128, ATT_SMEM>>>(
        Qhp, Qlp, Khp, Vhp, Op);

    split16_kernel<<<(n2 + 255) / 256, 256>>>(Op, Ahp, Alp, n2);
    tsplit16_kernel<<<tgrid, tblk>>>(Wo, Bhp);
    gemm_fp16x2_kernel<<<ggrid, 256, GEMM_SMEM>>>(Ahp, Alp, Bhp, out);
}

// round 17
// speedup vs baseline: 1.8067x; 1.1037x over previous
#include <cuda_runtime.h>
#include <cuda_fp16.h>
#include <cstdint>
#include <math.h>

#define S_LEN   2048
#define D_MODEL 2048
#define NH      16
#define DH      128
#define BATCH   2
#define TOKENS  (BATCH * S_LEN)   // 4096

// ---------------- scratch (device globals: allocation-free) ----------------
__device__ float g_Q[TOKENS * D_MODEL];
__device__ float g_K[TOKENS * D_MODEL];
__device__ __half g_Ahf[TOKENS * D_MODEL];           // fp16 split A (hi)
__device__ __half g_Alf[TOKENS * D_MODEL];           // fp16 split A (lo)
__device__ __half g_Bhf[D_MODEL * D_MODEL];          // fp16 transposed W [N][K]
__device__ __half g_Qh16[TOKENS * D_MODEL];
__device__ __half g_Ql16[TOKENS * D_MODEL];
__device__ __half g_Kh16[TOKENS * D_MODEL];
__device__ __half g_Vh16[TOKENS * D_MODEL];
__device__ float2 g_cs[S_LEN * 64];

// ---------------- common asm helpers ---------------------------------------
#define MMA16816F(d, a, b)                                                    \
    asm volatile(                                                             \
        "mma.sync.aligned.m16n8k16.row.col.f32.f16.f16.f32 "                  \
        "{%0,%1,%2,%3},{%4,%5,%6,%7},{%8,%9},{%0,%1,%2,%3};\n"                \
        : "+f"(d[0]), "+f"(d[1]), "+f"(d[2]), "+f"(d[3])                      \
        : "r"(a[0]), "r"(a[1]), "r"(a[2]), "r"(a[3]), "r"(b[0]), "r"(b[1]))

#define LDSM_X4(d0, d1, d2, d3, addr)                                         \
    asm volatile("ldmatrix.sync.aligned.m8n8.x4.shared.b16 {%0,%1,%2,%3}, [%4];" \
                 : "=r"(d0), "=r"(d1), "=r"(d2), "=r"(d3) : "r"(addr))

#define LDSM_X4_T(d0, d1, d2, d3, addr)                                       \
    asm volatile("ldmatrix.sync.aligned.m8n8.x4.trans.shared.b16 {%0,%1,%2,%3}, [%4];" \
                 : "=r"(d0), "=r"(d1), "=r"(d2), "=r"(d3) : "r"(addr))

#define CP16(dst, src)                                                        \
    asm volatile("cp.async.cg.shared.global [%0], [%1], 16;\n"                \
                 :: "r"(dst), "l"(src))
#define CP_COMMIT() asm volatile("cp.async.commit_group;\n" ::: "memory")
#define CP_WAIT0()  asm volatile("cp.async.wait_group 0;\n" ::: "memory")

__device__ __forceinline__ void split2pack16(float x, float y,
                                             uint32_t& hi, uint32_t& lo)
{
    __half hx = __float2half(x), hy = __float2half(y);
    __half lx = __float2half(x - __half2float(hx));
    __half ly = __float2half(y - __half2float(hy));
    __half2 th = __halves2half2(hx, hy);
    __half2 tl = __halves2half2(lx, ly);
    hi = *reinterpret_cast<uint32_t*>(&th);
    lo = *reinterpret_cast<uint32_t*>(&tl);
}

// ---------------- rope table (fp64 once, tiny) -----------------------------
__global__ void rope_table_kernel()
{
    int idx = blockIdx.x * blockDim.x + threadIdx.x;
    if (idx >= S_LEN * 64) return;
    int pos = idx >> 6;
    int i   = idx & 63;
    double inv = exp(-((double)(2 * i) / 128.0) * 9.210340371976184);
    double f   = (double)pos * inv;
    g_cs[idx] = make_float2((float)cos(f), (float)sin(f));
}

// ---------------- split fp32 -> fp16 hi/lo ---------------------------------
__global__ void split16_kernel(const float* __restrict__ x,
                               __half* __restrict__ hi,
                               __half* __restrict__ lo, int n2)
{
    int i = blockIdx.x * blockDim.x + threadIdx.x;
    if (i >= n2) return;
    float2 v = ((const float2*)x)[i];
    __half h0 = __float2half(v.x);
    __half h1 = __float2half(v.y);
    __half l0 = __float2half(v.x - __half2float(h0));
    __half l1 = __float2half(v.y - __half2float(h1));
    ((__half2*)hi)[i] = __halves2half2(h0, h1);
    ((__half2*)lo)[i] = __halves2half2(l0, l1);
}

// ---------------- rope + split fp16 hi/lo (for Q; no scale) ----------------
__global__ void rope_split16_kernel(const float* __restrict__ X,
                                    __half* __restrict__ Xh,
                                    __half* __restrict__ Xl)
{
    int idx = blockIdx.x * blockDim.x + threadIdx.x;
    if (idx >= TOKENS * NH * 64) return;
    int i  = idx & 63;
    int hh = (idx >> 6) & (NH - 1);
    int t  = idx >> 10;
    int pos = t & (S_LEN - 1);

    float2 cs = g_cs[pos * 64 + i];
    const float* p = X + (size_t)t * D_MODEL + hh * DH;
    float x1 = p[i];
    float x2 = p[i + 64];
    float y1 = x1 * cs.x - x2 * cs.y;
    float y2 = x2 * cs.x + x1 * cs.y;

    size_t o = (size_t)t * D_MODEL + hh * DH;
    __half h1 = __float2half(y1);
    __half h2 = __float2half(y2);
    Xh[o + i]      = h1;
    Xl[o + i]      = __float2half(y1 - __half2float(h1));
    Xh[o + i + 64] = h2;
    Xl[o + i + 64] = __float2half(y2 - __half2float(h2));
}

// ---------------- rope + fp16 hi only (for K) ------------------------------
__global__ void rope_half_kernel(const float* __restrict__ X,
                                 __half* __restrict__ Xh)
{
    int idx = blockIdx.x * blockDim.x + threadIdx.x;
    if (idx >= TOKENS * NH * 64) return;
    int i  = idx & 63;
    int hh = (idx >> 6) & (NH - 1);
    int t  = idx >> 10;
    int pos = t & (S_LEN - 1);

    float2 cs = g_cs[pos * 64 + i];
    const float* p = X + (size_t)t * D_MODEL + hh * DH;
    float x1 = p[i];
    float x2 = p[i + 64];
    size_t o = (size_t)t * D_MODEL + hh * DH;
    Xh[o + i]      = __float2half(x1 * cs.x - x2 * cs.y);
    Xh[o + i + 64] = __float2half(x2 * cs.x + x1 * cs.y);
}

// ---------------- transpose: W[K][N] -> WT[N][K] fp16 ----------------------
__global__ void tsplit16_kernel(const float* __restrict__ W,
                                __half* __restrict__ hiT)
{
    __shared__ float tile[32][33];
    int tx = threadIdx.x, ty = threadIdx.y;
    int x0 = blockIdx.x * 32, y0 = blockIdx.y * 32;
    #pragma unroll
    for (int j = 0; j < 32; j += 8)
        tile[ty + j][tx] = W[(size_t)(y0 + ty + j) * D_MODEL + x0 + tx];
    __syncthreads();
    #pragma unroll
    for (int j = 0; j < 32; j += 8) {
        float v = tile[tx][ty + j];
        hiT[(size_t)(x0 + ty + j) * D_MODEL + y0 + tx] = __float2half(v);
    }
}

// ---------------- GEMM common geometry -------------------------------------
#define TBM 128
#define TBN 128
#define TBK 32
#define TS  40                     // halves per row (padded)
#define TSZ (TBM * TS)
#define ASZ (TSZ * 2)              // bytes per array (10240)

// ---------------- fp16x2 GEMM (fp32 out) -----------------------------------
#define STAGE2_B (3 * ASZ)          // Ah, Al, Bh
#define GEMM2_SMEM (2 * STAGE2_B)   // 61440 B

__global__ void __launch_bounds__(256, 2) gemm_fp16x2_kernel(
    const __half* __restrict__ Ah, const __half* __restrict__ Al,
    const __half* __restrict__ BTh, float* __restrict__ C)
{
    const int K = D_MODEL, N = D_MODEL;
    extern __shared__ __half gsm[];
    const uint32_t cBase = (uint32_t)__cvta_generic_to_shared(gsm);

    const int t = threadIdx.x;
    const int bm = blockIdx.y, bn = blockIdx.x;
    const int warp = t >> 5, lane = t & 31;
    const int wm = warp >> 2, wn = warp & 3;
    const int g = lane >> 2, tq = lane & 3;

    const uint32_t aoff = (uint32_t)(((wm * 64 + (lane & 15)) * TS + ((lane >> 4) * 8)) * 2);
    const uint32_t boff = (uint32_t)(((wn * 32 + (lane & 7) + ((lane >> 4) * 8)) * TS
                                     + (((lane >> 3) & 1) * 8)) * 2);
    const int lr = t >> 2;
    const int lc = (t & 3) * 8;

    float acc[4][4][4];
    #pragma unroll
    for (int a = 0; a < 4; a++)
        #pragma unroll
        for (int b = 0; b < 4; b++)
            #pragma unroll
            for (int c = 0; c < 4; c++) acc[a][b][c] = 0.0f;

    const int KT = K / TBK;

    auto load_stage = [&](int kt, int buf) {
        uint32_t sb = cBase + (uint32_t)buf * STAGE2_B;
        int k0 = kt * TBK;
        #pragma unroll
        for (int rep = 0; rep < 2; rep++) {
            int r = lr + rep * 64;
            size_t ga = (size_t)(bm * TBM + r) * K + k0 + lc;
            size_t gb = (size_t)(bn * TBN + r) * K + k0 + lc;
            uint32_t ds = sb + (uint32_t)((r * TS + lc) * 2);
            CP16(ds,           Ah + ga);
            CP16(ds + ASZ,     Al + ga);
            CP16(ds + 2 * ASZ, BTh + gb);
        }
    };

    load_stage(0, 0);
    CP_COMMIT();

    for (int kt = 0; kt < KT; kt++) {
        CP_WAIT0();
        __syncthreads();
        if (kt + 1 < KT) {
            load_stage(kt + 1, (kt + 1) & 1);
            CP_COMMIT();
        }
        const uint32_t sb = cBase + (uint32_t)(kt & 1) * STAGE2_B;
        #pragma unroll
        for (int ks = 0; ks < 2; ks++) {
            const uint32_t kofs = ks * 32;
            uint32_t fah[4][4], fal[4][4], fbh[4][2];
            #pragma unroll
            for (int mf = 0; mf < 4; mf++) {
                uint32_t ad = sb + aoff + mf * (16 * TS * 2) + kofs;
                LDSM_X4(fah[mf][0], fah[mf][1], fah[mf][2], fah[mf][3], ad);
                LDSM_X4(fal[mf][0], fal[mf][1], fal[mf][2], fal[mf][3], ad + ASZ);
            }
            #pragma unroll
            for (int p = 0; p < 2; p++) {
                uint32_t bd = sb + 2 * ASZ + boff + p * (16 * TS * 2) + kofs;
                LDSM_X4(fbh[2*p][0], fbh[2*p][1], fbh[2*p+1][0], fbh[2*p+1][1], bd);
            }
            #pragma unroll
            for (int mf = 0; mf < 4; mf++)
                #pragma unroll
                for (int nf = 0; nf < 4; nf++) {
                    MMA16816F(acc[mf][nf], fah[mf], fbh[nf]);
                    MMA16816F(acc[mf][nf], fal[mf], fbh[nf]);
                }
        }
    }

    #pragma unroll
    for (int mf = 0; mf < 4; mf++) {
        int row = bm * TBM + wm * 64 + mf * 16 + g;
        #pragma unroll
        for (int nf = 0; nf < 4; nf++) {
            int col = bn * TBN + wn * 32 + nf * 8 + tq * 2;
            *(float2*)&C[(size_t)row * N + col] =
                make_float2(acc[mf][nf][0], acc[mf][nf][1]);
            *(float2*)&C[(size_t)(row + 8) * N + col] =
                make_float2(acc[mf][nf][2], acc[mf][nf][3]);
        }
    }
}

// ---------------- fp16x2 GEMM variant: __half output (for V) ---------------
__global__ void __launch_bounds__(256, 2) gemm_fp16x2h_kernel(
    const __half* __restrict__ Ah, const __half* __restrict__ Al,
    const __half* __restrict__ BTh, __half* __restrict__ C)
{
    const int K = D_MODEL, N = D_MODEL;
    extern __shared__ __half gsm[];
    const uint32_t cBase = (uint32_t)__cvta_generic_to_shared(gsm);

    const int t = threadIdx.x;
    const int bm = blockIdx.y, bn = blockIdx.x;
    const int warp = t >> 5, lane = t & 31;
    const int wm = warp >> 2, wn = warp & 3;
    const int g = lane >> 2, tq = lane & 3;

    const uint32_t aoff = (uint32_t)(((wm * 64 + (lane & 15)) * TS + ((lane >> 4) * 8)) * 2);
    const uint32_t boff = (uint32_t)(((wn * 32 + (lane & 7) + ((lane >> 4) * 8)) * TS
                                     + (((lane >> 3) & 1) * 8)) * 2);
    const int lr = t >> 2;
    const int lc = (t & 3) * 8;

    float acc[4][4][4];
    #pragma unroll
    for (int a = 0; a < 4; a++)
        #pragma unroll
        for (int b = 0; b < 4; b++)
            #pragma unroll
            for (int c = 0; c < 4; c++) acc[a][b][c] = 0.0f;

    const int KT = K / TBK;

    auto load_stage = [&](int kt, int buf) {
        uint32_t sb = cBase + (uint32_t)buf * STAGE2_B;
        int k0 = kt * TBK;
        #pragma unroll
        for (int rep = 0; rep < 2; rep++) {
            int r = lr + rep * 64;
            size_t ga = (size_t)(bm * TBM + r) * K + k0 + lc;
            size_t gb = (size_t)(bn * TBN + r) * K + k0 + lc;
            uint32_t ds = sb + (uint32_t)((r * TS + lc) * 2);
            CP16(ds,           Ah + ga);
            CP16(ds + ASZ,     Al + ga);
            CP16(ds + 2 * ASZ, BTh + gb);
        }
    };

    load_stage(0, 0);
    CP_COMMIT();

    for (int kt = 0; kt < KT; kt++) {
        CP_WAIT0();
        __syncthreads();
        if (kt + 1 < KT) {
            load_stage(kt + 1, (kt + 1) & 1);
            CP_COMMIT();
        }
        const uint32_t sb = cBase + (uint32_t)(kt & 1) * STAGE2_B;
        #pragma unroll
        for (int ks = 0; ks < 2; ks++) {
            const uint32_t kofs = ks * 32;
            uint32_t fah[4][4], fal[4][4], fbh[4][2];
            #pragma unroll
            for (int mf = 0; mf < 4; mf++) {
                uint32_t ad = sb + aoff + mf * (16 * TS * 2) + kofs;
                LDSM_X4(fah[mf][0], fah[mf][1], fah[mf][2], fah[mf][3], ad);
                LDSM_X4(fal[mf][0], fal[mf][1], fal[mf][2], fal[mf][3], ad + ASZ);
            }
            #pragma unroll
            for (int p = 0; p < 2; p++) {
                uint32_t bd = sb + 2 * ASZ + boff + p * (16 * TS * 2) + kofs;
                LDSM_X4(fbh[2*p][0], fbh[2*p][1], fbh[2*p+1][0], fbh[2*p+1][1], bd);
            }
            #pragma unroll
            for (int mf = 0; mf < 4; mf++)
                #pragma unroll
                for (int nf = 0; nf < 4; nf++) {
                    MMA16816F(acc[mf][nf], fah[mf], fbh[nf]);
                    MMA16816F(acc[mf][nf], fal[mf], fbh[nf]);
                }
        }
    }

    #pragma unroll
    for (int mf = 0; mf < 4; mf++) {
        int row = bm * TBM + wm * 64 + mf * 16 + g;
        #pragma unroll
        for (int nf = 0; nf < 4; nf++) {
            int col = bn * TBN + wn * 32 + nf * 8 + tq * 2;
            *(__half2*)&C[(size_t)row * N + col] =
                __halves2half2(__float2half(acc[mf][nf][0]), __float2half(acc[mf][nf][1]));
            *(__half2*)&C[(size_t)(row + 8) * N + col] =
                __halves2half2(__float2half(acc[mf][nf][2]), __float2half(acc[mf][nf][3]));
        }
    }
}

// ---------------- fp16x1 GEMM (single product; for K) ----------------------
#define STAGE1_B (2 * ASZ)          // Ah, Bh
#define GEMM1_SMEM (2 * STAGE1_B)   // 40960 B

__global__ void __launch_bounds__(256, 2) gemm_fp16x1_kernel(
    const __half* __restrict__ Ah, const __half* __restrict__ BTh,
    float* __restrict__ C)
{
    const int K = D_MODEL, N = D_MODEL;
    extern __shared__ __half gsm[];
    const uint32_t cBase = (uint32_t)__cvta_generic_to_shared(gsm);

    const int t = threadIdx.x;
    const int bm = blockIdx.y, bn = blockIdx.x;
    const int warp = t >> 5, lane = t & 31;
    const int wm = warp >> 2, wn = warp & 3;
    const int g = lane >> 2, tq = lane & 3;

    const uint32_t aoff = (uint32_t)(((wm * 64 + (lane & 15)) * TS + ((lane >> 4) * 8)) * 2);
    const uint32_t boff = (uint32_t)(((wn * 32 + (lane & 7) + ((lane >> 4) * 8)) * TS
                                     + (((lane >> 3) & 1) * 8)) * 2);
    const int lr = t >> 2;
    const int lc = (t & 3) * 8;

    float acc[4][4][4];
    #pragma unroll
    for (int a = 0; a < 4; a++)
        #pragma unroll
        for (int b = 0; b < 4; b++)
            #pragma unroll
            for (int c = 0; c < 4; c++) acc[a][b][c] = 0.0f;

    const int KT = K / TBK;

    auto load_stage = [&](int kt, int buf) {
        uint32_t sb = cBase + (uint32_t)buf * STAGE1_B;
        int k0 = kt * TBK;
        #pragma unroll
        for (int rep = 0; rep < 2; rep++) {
            int r = lr + rep * 64;
            size_t ga = (size_t)(bm * TBM + r) * K + k0 + lc;
            size_t gb = (size_t)(bn * TBN + r) * K + k0 + lc;
            uint32_t ds = sb + (uint32_t)((r * TS + lc) * 2);
            CP16(ds,       Ah + ga);
            CP16(ds + ASZ, BTh + gb);
        }
    };

    load_stage(0, 0);
    CP_COMMIT();

    for (int kt = 0; kt < KT; kt++) {
        CP_WAIT0();
        __syncthreads();
        if (kt + 1 < KT) {
            load_stage(kt + 1, (kt + 1) & 1);
            CP_COMMIT();
        }
        const uint32_t sb = cBase + (uint32_t)(kt & 1) * STAGE1_B;
        #pragma unroll
        for (int ks = 0; ks < 2; ks++) {
            const uint32_t kofs = ks * 32;
            uint32_t fah[4][4], fbh[4][2];
            #pragma unroll
            for (int mf = 0; mf < 4; mf++) {
                uint32_t ad = sb + aoff + mf * (16 * TS * 2) + kofs;
                LDSM_X4(fah[mf][0], fah[mf][1], fah[mf][2], fah[mf][3], ad);
            }
            #pragma unroll
            for (int p = 0; p < 2; p++) {
                uint32_t bd = sb + ASZ + boff + p * (16 * TS * 2) + kofs;
                LDSM_X4(fbh[2*p][0], fbh[2*p][1], fbh[2*p+1][0], fbh[2*p+1][1], bd);
            }
            #pragma unroll
            for (int mf = 0; mf < 4; mf++)
                #pragma unroll
                for (int nf = 0; nf < 4; nf++)
                    MMA16816F(acc[mf][nf], fah[mf], fbh[nf]);
        }
    }

    #pragma unroll
    for (int mf = 0; mf < 4; mf++) {
        int row = bm * TBM + wm * 64 + mf * 16 + g;
        #pragma unroll
        for (int nf = 0; nf < 4; nf++) {
            int col = bn * TBN + wn * 32 + nf * 8 + tq * 2;
            *(float2*)&C[(size_t)row * N + col] =
                make_float2(acc[mf][nf][0], acc[mf][nf][1]);
            *(float2*)&C[(size_t)(row + 8) * N + col] =
                make_float2(acc[mf][nf][2], acc[mf][nf][3]);
        }
    }
}

// ---------------- tensor-core flash attention (fp16x2, causal, BQ=64) ------
#define AT_SD 136
#define AT_TILE (64 * AT_SD)
#define ATT_SMEM (4 * AT_TILE * 2)   // Qh,Ql,Kh,Vh = 69632 B
#define SM_SCALE 0.08838834764831845f

__global__ void __launch_bounds__(128) attn_tc_kernel(
    const __half* __restrict__ Qh, const __half* __restrict__ Ql,
    const __half* __restrict__ Kh, const __half* __restrict__ Vh,
    __half* __restrict__ Oh, __half* __restrict__ Ol)
{
    const int b = blockIdx.z, h = blockIdx.y, qb = blockIdx.x;
    const int tid = threadIdx.x, warp = tid >> 5, lane = tid & 31;
    const int g = lane >> 2, tq = lane & 3;

    extern __shared__ __half sh[];
    __half* sQh = sh;
    __half* sQl = sQh + AT_TILE;
    __half* sKh = sQl + AT_TILE;
    __half* sVh = sKh + AT_TILE;

    const size_t base = ((size_t)b * S_LEN) * D_MODEL + (size_t)h * DH;

    for (int i = tid; i < 64 * 16; i += 128) {
        int r = i >> 4, c = (i & 15) << 3;
        size_t src = base + (size_t)(qb * 64 + r) * D_MODEL + c;
        *(uint4*)&sQh[r * AT_SD + c] = *(const uint4*)(Qh + src);
        *(uint4*)&sQl[r * AT_SD + c] = *(const uint4*)(Ql + src);
    }

    float o[16][4];
    #pragma unroll
    for (int nf = 0; nf < 16; nf++)
        #pragma unroll
        for (int c = 0; c < 4; c++) o[nf][c] = 0.0f;
    float mr0 = -INFINITY, mr1 = -INFINITY, lr0 = 0.0f, lr1 = 0.0f;

    const uint32_t cQh = (uint32_t)__cvta_generic_to_shared(sQh);
    const uint32_t cQl = (uint32_t)__cvta_generic_to_shared(sQl);
    const uint32_t cKh = (uint32_t)__cvta_generic_to_shared(sKh);
    const uint32_t cVh = (uint32_t)__cvta_generic_to_shared(sVh);
    const uint32_t aoff  = (uint32_t)(((warp * 16 + (lane & 15)) * AT_SD + ((lane >> 4) * 8)) * 2);
    const uint32_t boffK = (uint32_t)((((lane & 7) + ((lane >> 4) * 8)) * AT_SD
                                      + (((lane >> 3) & 1) * 8)) * 2);
    const uint32_t boffVt = (uint32_t)(((lane & 15) * AT_SD + ((lane >> 4) * 8)) * 2);

    for (int kb = 0; kb <= qb; kb++) {
        __syncthreads();
        for (int i = tid; i < 64 * 16; i += 128) {
            int r = i >> 4, c = (i & 15) << 3;
            size_t src = base + (size_t)(kb * 64 + r) * D_MODEL + c;
            *(uint4*)&sKh[r * AT_SD + c] = *(const uint4*)(Kh + src);
            *(uint4*)&sVh[r * AT_SD + c] = *(const uint4*)(Vh + src);
        }
        __syncthreads();

        float s[8][4];
        #pragma unroll
        for (int tt = 0; tt < 8; tt++)
            #pragma unroll
            for (int c = 0; c < 4; c++) s[tt][c] = 0.0f;

        #pragma unroll
        for (int ks = 0; ks < 8; ks++) {
            uint32_t qh[4], ql[4];
            LDSM_X4(qh[0], qh[1], qh[2], qh[3], cQh + aoff + ks * 32);
            LDSM_X4(ql[0], ql[1], ql[2], ql[3], cQl + aoff + ks * 32);
            #pragma unroll
            for (int p = 0; p < 4; p++) {
                uint32_t kh[4];
                uint32_t bd = boffK + p * (16 * AT_SD * 2) + ks * 32;
                LDSM_X4(kh[0], kh[1], kh[2], kh[3], cKh + bd);
                uint32_t bh0[2] = {kh[0], kh[1]}, bh1[2] = {kh[2], kh[3]};
                MMA16816F(s[2*p],     qh, bh0);
                MMA16816F(s[2*p],     ql, bh0);
                MMA16816F(s[2*p + 1], qh, bh1);
                MMA16816F(s[2*p + 1], ql, bh1);
            }
        }

        #pragma unroll
        for (int tt = 0; tt < 8; tt++)
            #pragma unroll
            for (int c = 0; c < 4; c++) s[tt][c] *= SM_SCALE;

        if (kb == qb) {
            int r0 = warp * 16 + g, r1 = r0 + 8;
            #pragma unroll
            for (int tt = 0; tt < 8; tt++) {
                int c0 = tt * 8 + tq * 2;
                if (c0     > r0) s[tt][0] = -INFINITY;
                if (c0 + 1 > r0) s[tt][1] = -INFINITY;
                if (c0     > r1) s[tt][2] = -INFINITY;
                if (c0 + 1 > r1) s[tt][3] = -INFINITY;
            }
        }

        float mx0 = -INFINITY, mx1 = -INFINITY;
        #pragma unroll
        for (int tt = 0; tt < 8; tt++) {
            mx0 = fmaxf(mx0, fmaxf(s[tt][0], s[tt][1]));
            mx1 = fmaxf(mx1, fmaxf(s[tt][2], s[tt][3]));
        }
        mx0 = fmaxf(mx0, __shfl_xor_sync(0xffffffffu, mx0, 1));
        mx0 = fmaxf(mx0, __shfl_xor_sync(0xffffffffu, mx0, 2));
        mx1 = fmaxf(mx1, __shfl_xor_sync(0xffffffffu, mx1, 1));
        mx1 = fmaxf(mx1, __shfl_xor_sync(0xffffffffu, mx1, 2));

        float mn0 = fmaxf(mr0, mx0), mn1 = fmaxf(mr1, mx1);
        float al0 = __expf(mr0 - mn0), al1 = __expf(mr1 - mn1);
        float sum0 = 0.0f, sum1 = 0.0f;
        #pragma unroll
        for (int tt = 0; tt < 8; tt++) {
            s[tt][0] = __expf(s[tt][0] - mn0);
            s[tt][1] = __expf(s[tt][1] - mn0);
            s[tt][2] = __expf(s[tt][2] - mn1);
            s[tt][3] = __expf(s[tt][3] - mn1);
            sum0 += s[tt][0] + s[tt][1];
            sum1 += s[tt][2] + s[tt][3];
        }
        sum0 += __shfl_xor_sync(0xffffffffu, sum0, 1);
        sum0 += __shfl_xor_sync(0xffffffffu, sum0, 2);
        sum1 += __shfl_xor_sync(0xffffffffu, sum1, 1);
        sum1 += __shfl_xor_sync(0xffffffffu, sum1, 2);
        lr0 = lr0 * al0 + sum0;
        lr1 = lr1 * al1 + sum1;
        mr0 = mn0;
        mr1 = mn1;
        #pragma unroll
        for (int nf = 0; nf < 16; nf++) {
            o[nf][0] *= al0; o[nf][1] *= al0;
            o[nf][2] *= al1; o[nf][3] *= al1;
        }

        #pragma unroll
        for (int j = 0; j < 4; j++) {
            uint32_t ph[4], pl[4];
            split2pack16(s[2*j][0],     s[2*j][1],     ph[0], pl[0]);
            split2pack16(s[2*j][2],     s[2*j][3],     ph[1], pl[1]);
            split2pack16(s[2*j + 1][0], s[2*j + 1][1], ph[2], pl[2]);
            split2pack16(s[2*j + 1][2], s[2*j + 1][3], ph[3], pl[3]);
            #pragma unroll
            for (int dtile = 0; dtile < 8; dtile++) {
                uint32_t vh4[4];
                uint32_t bd = boffVt + (uint32_t)((j * 16 * AT_SD + dtile * 16) * 2);
                LDSM_X4_T(vh4[0], vh4[1], vh4[2], vh4[3], cVh + bd);
                uint32_t bh0[2] = {vh4[0], vh4[1]}, bh1[2] = {vh4[2], vh4[3]};
                MMA16816F(o[2*dtile],     ph, bh0);
                MMA16816F(o[2*dtile],     pl, bh0);
                MMA16816F(o[2*dtile + 1], ph, bh1);
                MMA16816F(o[2*dtile + 1], pl, bh1);
            }
        }
    }

    // epilogue: write fp16 hi/lo directly (A-side of the Wo GEMM)
    float inv0 = 1.0f / lr0, inv1 = 1.0f / lr1;
    int r0 = qb * 64 + warp * 16 + g;
    #pragma unroll
    for (int dtile = 0; dtile < 8; dtile++) {
        #pragma unroll
        for (int u = 0; u < 2; u++) {
            int nf = 2 * dtile + u;
            int c = dtile * 16 + u * 8 + tq * 2;
            uint32_t hi0, lo0, hi1, lo1;
            split2pack16(o[nf][0] * inv0, o[nf][1] * inv0, hi0, lo0);
            split2pack16(o[nf][2] * inv1, o[nf][3] * inv1, hi1, lo1);
            size_t i0 = base + (size_t)r0 * D_MODEL + c;
            size_t i1 = base + (size_t)(r0 + 8) * D_MODEL + c;
            *(uint32_t*)&Oh[i0] = hi0;
            *(uint32_t*)&Ol[i0] = lo0;
            *(uint32_t*)&Oh[i1] = hi1;
            *(uint32_t*)&Ol[i1] = lo1;
        }
    }
}

// ---------------- launch ----------------------------------------------------
extern "C" void kernel_launch(void* const* d_in, const int* in_sizes, int n_in,
                              void* d_out, int out_size)
{
    (void)in_sizes; (void)n_in; (void)out_size;
    const float* hidden = (const float*)d_in[0];
    const float* Wq = (const float*)d_in[3];
    const float* Wk = (const float*)d_in[4];
    const float* Wv = (const float*)d_in[5];
    const float* Wo = (const float*)d_in[6];
    float* out = (float*)d_out;

    float *Qp, *Kp;
    __half *Ahp, *Alp, *Bhp;
    __half *Qhp, *Qlp, *Khp, *Vhp;
    cudaGetSymbolAddress((void**)&Qp, g_Q);
    cudaGetSymbolAddress((void**)&Kp, g_K);
    cudaGetSymbolAddress((void**)&Ahp, g_Ahf);
    cudaGetSymbolAddress((void**)&Alp, g_Alf);
    cudaGetSymbolAddress((void**)&Bhp, g_Bhf);
    cudaGetSymbolAddress((void**)&Qhp, g_Qh16);
    cudaGetSymbolAddress((void**)&Qlp, g_Ql16);
    cudaGetSymbolAddress((void**)&Khp, g_Kh16);
    cudaGetSymbolAddress((void**)&Vhp, g_Vh16);

    rope_table_kernel<<<(S_LEN * 64 + 255) / 256, 256>>>();

    int n2 = TOKENS * D_MODEL / 2;
    split16_kernel<<<(n2 + 255) / 256, 256>>>(hidden, Ahp, Alp, n2);

    dim3 tgrid(D_MODEL / 32, D_MODEL / 32);
    dim3 tblk(32, 8);
    dim3 ggrid(D_MODEL / TBN, TOKENS / TBM);

    cudaFuncSetAttribute(gemm_fp16x2_kernel,
                         cudaFuncAttributeMaxDynamicSharedMemorySize, GEMM2_SMEM);
    cudaFuncSetAttribute(gemm_fp16x2h_kernel,
                         cudaFuncAttributeMaxDynamicSharedMemorySize, GEMM2_SMEM);
    cudaFuncSetAttribute(gemm_fp16x1_kernel,
                         cudaFuncAttributeMaxDynamicSharedMemorySize, GEMM1_SMEM);

    // Q: 2-product (feeds hi/lo attention path, needs 22-bit)
    tsplit16_kernel<<<tgrid, tblk>>>(Wq, Bhp);
    gemm_fp16x2_kernel<<<ggrid, 256, GEMM2_SMEM>>>(Ahp, Alp, Bhp, Qp);
    // K: 1-product (consumed as fp16-hi only)
    tsplit16_kernel<<<tgrid, tblk>>>(Wk, Bhp);
    gemm_fp16x1_kernel<<<ggrid, 256, GEMM1_SMEM>>>(Ahp, Bhp, Kp);
    // V: 2-product, direct __half output
    tsplit16_kernel<<<tgrid, tblk>>>(Wv, Bhp);
    gemm_fp16x2h_kernel<<<ggrid, 256, GEMM2_SMEM>>>(Ahp, Alp, Bhp, Vhp);

    int nrope = TOKENS * NH * 64;
    rope_split16_kernel<<<(nrope + 255) / 256, 256>>>(Qp, Qhp, Qlp);
    rope_half_kernel<<<(nrope + 255) / 256, 256>>>(Kp, Khp);

    cudaFuncSetAttribute(attn_tc_kernel,
                         cudaFuncAttributeMaxDynamicSharedMemorySize, ATT_SMEM);
    attn_tc_kernel<<<dim3(S_LEN / 64, NH, BATCH), 128, ATT_SMEM>>>(
        Qhp, Qlp, Khp, Vhp, Ahp, Alp);   // epilogue overwrites A-side buffers

    tsplit16_kernel<<<tgrid, tblk>>>(Wo, Bhp);
    gemm_fp16x2_kernel<<<ggrid, 256, GEMM2_SMEM>>>(Ahp, Alp, Bhp, out);
}